// round 8
// baseline (speedup 1.0000x reference)
#include <cuda_runtime.h>
#include <cuda_bf16.h>
#include <math.h>
#include <stdint.h>

// ---------------- problem dims ----------------
#define TT    10
#define BBs   4
#define CCh   256
#define NP    256
#define TRR   40
#define HIDD  1024
#define EPSL  1e-5f

#define BCN   (BBs*CCh*NP)       // 262144
#define BHN   (BBs*HIDD*NP)      // 1048576
#define S_TBCN  (TT*BCN)
#define S_TRBCN (TRR*BBs*CCh*NP)

// packed fp32x2 (conv1 path)
#define FMA2(d,a,b)  asm("fma.rn.f32x2 %0, %1, %2, %0;" : "+l"(d) : "l"(a), "l"(b))
#define PACK2(d,x)   asm("mov.b64 %0, {%1, %1};" : "=l"(d) : "r"(__float_as_uint(x)))
#define UNPACK2(lo,hi,v) asm("mov.b64 {%0, %1}, %2;" : "=r"(lo), "=r"(hi) : "l"(v))

// ---------------- scratch ----------------
__device__ float g_bufA[S_TRBCN];
__device__ float g_bufB[S_TRBCN];
__device__ float g_spk1[3*S_TRBCN];
__device__ float g_spk2[3*S_TBCN];
__device__ float g_y[S_TBCN];
__device__ float g_o[S_TBCN];
__device__ float g_h[S_TBCN];
__device__ float g_ktv[TT*BBs*16*256];
__device__ float g_scale[HIDD];
__device__ float g_shift[HIDD];
__device__ float g_t1s[TRR], g_t1h[TRR];
__device__ float g_t2s[TT],  g_t2h[TT];
__device__ __nv_bfloat16 g_Aimg[2359296];    // weight split tile images
__device__ __nv_bfloat16 g_Bimg[10485760];   // activation split tile images

#define A_QKV 0
#define A_PROJ 589824
#define A_FC1 786432
#define A_FC2 1572864

// ---------------- exact 3-way bf16 split ----------------
__device__ __forceinline__ void split3(float x, __nv_bfloat16& h, __nv_bfloat16& m, __nv_bfloat16& l) {
    h = __float2bfloat16_rn(x);
    float r1 = x - __bfloat162float(h);
    m = __float2bfloat16_rn(r1);
    float r2 = r1 - __bfloat162float(m);
    l = __float2bfloat16_rn(r2);
}

// ---------------- BN folding ----------------
__global__ void prep_bn_kernel(const float* __restrict__ bnp, const float* __restrict__ bias,
                               float* __restrict__ scale, float* __restrict__ shift, int cnum)
{
    int i = blockIdx.x * blockDim.x + threadIdx.x;
    if (i >= cnum) return;
    float g  = bnp[i];
    float be = bnp[cnum + i];
    float m  = bnp[2*cnum + i];
    float v  = bnp[3*cnum + i];
    float s  = g / sqrtf(v + EPSL);
    float sh = be - m * s;
    if (bias) sh += bias[i] * s;
    scale[i] = s;
    shift[i] = sh;
}

// ---------------- weight split prep: W fp32 (O,K) -> 3 bf16 plain tile images ----------------
// image tile: 128 rows x 64 k, row-major k-contiguous (8192 elems/tile)
__global__ void w_prep_kernel(const float* __restrict__ W, __nv_bfloat16* __restrict__ dst,
                              int O, int K, int nMtot, int mBase)
{
    int kpairs = K >> 1;
    int tid = blockIdx.x * blockDim.x + threadIdx.x;
    if (tid >= O * kpairs) return;
    int o = tid / kpairs, kp = tid % kpairs;
    int k = kp * 2;
    float v0 = W[(size_t)o * K + k], v1 = W[(size_t)o * K + k + 1];
    __nv_bfloat16 h0, m0, l0, h1, m1, l1;
    split3(v0, h0, m0, l0);
    split3(v1, h1, m1, l1);
    int nC = K >> 6;
    int mt = mBase + (o >> 7), r = o & 127, ch = k >> 6, kk = k & 63;
    uint32_t off = (uint32_t)(r * 64 + kk);
    __nv_bfloat162 p;
    p.x = h0; p.y = h1;
    *(__nv_bfloat162*)&dst[((size_t)((0 * nMtot + mt) * nC + ch)) * 8192 + off] = p;
    p.x = m0; p.y = m1;
    *(__nv_bfloat162*)&dst[((size_t)((1 * nMtot + mt) * nC + ch)) * 8192 + off] = p;
    p.x = l0; p.y = l1;
    *(__nv_bfloat162*)&dst[((size_t)((2 * nMtot + mt) * nC + ch)) * 8192 + off] = p;
}

// ---------------- activation split prep (3-split, transpose to [n][k]) ----------------
// image tile: 256 rows (n) x 64 k (16384 elems/tile)
__global__ void x3_prep_kernel(const float* __restrict__ In, __nv_bfloat16* __restrict__ Bimg, int K)
{
    __shared__ float s[64][65];
    int ch = blockIdx.x, nb = blockIdx.y, tb = blockIdx.z;
    int nC = K >> 6;
    int tid = threadIdx.x;
    const float* src = In + ((size_t)tb * K + ch * 64) * 256 + nb * 64;
    for (int idx = tid; idx < 64 * 64; idx += 256) {
        int kk = idx >> 6, nl = idx & 63;
        s[kk][nl] = src[(size_t)kk * 256 + nl];
    }
    __syncthreads();
    for (int idx = tid; idx < 64 * 32; idx += 256) {
        int nl = idx >> 5, kp = idx & 31;
        float v0 = s[kp * 2][nl], v1 = s[kp * 2 + 1][nl];
        __nv_bfloat16 h0, m0, l0, h1, m1, l1;
        split3(v0, h0, m0, l0);
        split3(v1, h1, m1, l1);
        int row = nb * 64 + nl;
        uint32_t off = (uint32_t)(row * 64 + kp * 2);
        __nv_bfloat162 p;
        p.x = h0; p.y = h1;
        *(__nv_bfloat162*)&Bimg[((size_t)((tb * 3 + 0) * nC + ch)) * 16384 + off] = p;
        p.x = m0; p.y = m1;
        *(__nv_bfloat162*)&Bimg[((size_t)((tb * 3 + 1) * nC + ch)) * 16384 + off] = p;
        p.x = l0; p.y = l1;
        *(__nv_bfloat162*)&Bimg[((size_t)((tb * 3 + 2) * nC + ch)) * 16384 + off] = p;
    }
}

// 1-split variant (binary spike inputs: bf16 exact)
__global__ void x1_prep_kernel(const float* __restrict__ In, __nv_bfloat16* __restrict__ Bimg, int K)
{
    __shared__ float s[64][65];
    int ch = blockIdx.x, nb = blockIdx.y, tb = blockIdx.z;
    int nC = K >> 6;
    int tid = threadIdx.x;
    const float* src = In + ((size_t)tb * K + ch * 64) * 256 + nb * 64;
    for (int idx = tid; idx < 64 * 64; idx += 256) {
        int kk = idx >> 6, nl = idx & 63;
        s[kk][nl] = src[(size_t)kk * 256 + nl];
    }
    __syncthreads();
    for (int idx = tid; idx < 64 * 32; idx += 256) {
        int nl = idx >> 5, kp = idx & 31;
        int row = nb * 64 + nl;
        uint32_t off = (uint32_t)(row * 64 + kp * 2);
        __nv_bfloat162 p;
        p.x = __float2bfloat16_rn(s[kp * 2][nl]);
        p.y = __float2bfloat16_rn(s[kp * 2 + 1][nl]);
        *(__nv_bfloat162*)&Bimg[((size_t)(tb * nC + ch)) * 16384 + off] = p;
    }
}

// ---------------- warp-MMA (bf16 HMMA) split GEMM + BN epilogue ----------------
// CTA: 512 thr = 16 warps (4m x 4n), warp tile 32x64, CTA tile 128(M) x 256(N).
// Accumulates sum over split-term pairs (i+j<=2) and K chunks entirely in registers.
#define PITCH 36   // smem row pitch in 32-bit words (72 bf16)
__global__ __launch_bounds__(512)
void mma_gemm_kernel(const __nv_bfloat16* __restrict__ Aimg,
                     const __nv_bfloat16* __restrict__ Bimg,
                     float* __restrict__ Out, int O, int nM, int nChunk, int nB,
                     const float* __restrict__ scale, const float* __restrict__ shift)
{
    __shared__ uint32_t sA[128 * PITCH];   // [m][k] 128x64 bf16, padded
    __shared__ uint32_t sB[256 * PITCH];   // [n][k] 256x64 bf16, padded
    int mtile = blockIdx.x, tb = blockIdx.y;
    int tid = threadIdx.x, wid = tid >> 5, lane = tid & 31;
    int g = lane >> 2, t = lane & 3;
    int wm = wid >> 2, wn = wid & 3;        // warp grid 4x4
    int mBase = wm * 32, nBase = wn * 64;

    float acc[2][8][4];
#pragma unroll
    for (int mi = 0; mi < 2; mi++)
#pragma unroll
        for (int ni = 0; ni < 8; ni++)
#pragma unroll
            for (int r = 0; r < 4; r++) acc[mi][ni][r] = 0.f;

    for (int i = 0; i < 3; i++) {
        for (int j = 0; j < nB; j++) {
            if (i + j > 2) continue;
            for (int ch = 0; ch < nChunk; ch++) {
                const uint4* as = (const uint4*)(Aimg + ((size_t)((i * nM + mtile) * nChunk + ch)) * 8192);
                const uint4* bs = (const uint4*)(Bimg + ((size_t)((tb * nB + j) * nChunk + ch)) * 16384);
                __syncthreads();
                // A: 1024 uint4 (rows of 8 uint4) ; B: 2048 uint4
#pragma unroll
                for (int q = 0; q < 2; q++) {
                    int idx = tid + q * 512;
                    int row = idx >> 3, col = idx & 7;
                    *(uint4*)&sA[row * PITCH + col * 4] = as[idx];
                }
#pragma unroll
                for (int q = 0; q < 4; q++) {
                    int idx = tid + q * 512;
                    int row = idx >> 3, col = idx & 7;
                    *(uint4*)&sB[row * PITCH + col * 4] = bs[idx];
                }
                __syncthreads();

#pragma unroll
                for (int k0 = 0; k0 < 4; k0++) {      // k-step = 16 bf16 = 8 words
                    int kw = k0 * 8;
                    uint32_t a[2][4];
#pragma unroll
                    for (int mi = 0; mi < 2; mi++) {
                        int r0 = mBase + mi * 16 + g;
                        a[mi][0] = sA[r0 * PITCH + kw + t];
                        a[mi][1] = sA[(r0 + 8) * PITCH + kw + t];
                        a[mi][2] = sA[r0 * PITCH + kw + t + 4];
                        a[mi][3] = sA[(r0 + 8) * PITCH + kw + t + 4];
                    }
#pragma unroll
                    for (int ni = 0; ni < 8; ni++) {
                        int n0 = nBase + ni * 8 + g;
                        uint32_t b0 = sB[n0 * PITCH + kw + t];
                        uint32_t b1 = sB[n0 * PITCH + kw + t + 4];
#pragma unroll
                        for (int mi = 0; mi < 2; mi++) {
                            asm volatile(
                                "mma.sync.aligned.m16n8k16.row.col.f32.bf16.bf16.f32 "
                                "{%0,%1,%2,%3}, {%4,%5,%6,%7}, {%8,%9}, {%0,%1,%2,%3};"
                                : "+f"(acc[mi][ni][0]), "+f"(acc[mi][ni][1]),
                                  "+f"(acc[mi][ni][2]), "+f"(acc[mi][ni][3])
                                : "r"(a[mi][0]), "r"(a[mi][1]), "r"(a[mi][2]), "r"(a[mi][3]),
                                  "r"(b0), "r"(b1));
                        }
                    }
                }
            }
        }
    }

    // epilogue: D[m][n]*scale[o]+shift[o]
#pragma unroll
    for (int mi = 0; mi < 2; mi++) {
        int o1 = mtile * 128 + mBase + mi * 16 + g;
        int o2 = o1 + 8;
        float sc1 = scale[o1], sh1 = shift[o1];
        float sc2 = scale[o2], sh2 = shift[o2];
        float* p1 = Out + ((size_t)tb * O + o1) * 256;
        float* p2 = Out + ((size_t)tb * O + o2) * 256;
#pragma unroll
        for (int ni = 0; ni < 8; ni++) {
            int n0 = nBase + ni * 8 + 2 * t;
            float2 v1, v2;
            v1.x = acc[mi][ni][0] * sc1 + sh1;
            v1.y = acc[mi][ni][1] * sc1 + sh1;
            v2.x = acc[mi][ni][2] * sc2 + sh2;
            v2.y = acc[mi][ni][3] * sc2 + sh2;
            *(float2*)(p1 + n0) = v1;
            *(float2*)(p2 + n0) = v2;
        }
    }
}

// ---------------- TIM conv1 + BN + fused LIF1 ----------------
__global__ __launch_bounds__(256)
void tim_conv1_kernel(const float* __restrict__ in, const float* __restrict__ wup,
                      const float* __restrict__ sc, const float* __restrict__ sh,
                      float* __restrict__ out)
{
    __shared__ __align__(16) float sW[2][1080];
    __shared__ float sIn[2][3][18*19];
    int c  = blockIdx.x;
    int b  = blockIdx.y;
    int br = blockIdx.z;
    int tid = threadIdx.x;
    const float* inb = in + ((size_t)b * 768 + br * 256) * NP;

    {
        float ip[4], wpre[5];
#pragma unroll
        for (int j = 0; j < 4; j++) {
            int i = tid + j * 256;
            float v = 0.f;
            if (i < 972) {
                int dc = i / 324, rem = i % 324;
                int hh = rem / 18, ww = rem % 18;
                int ci = c + dc - 1;
                int hy = hh - 1, wx = ww - 1;
                if (ci >= 0 && ci < CCh && hy >= 0 && hy < 16 && wx >= 0 && wx < 16)
                    v = inb[(size_t)ci * NP + hy * 16 + wx];
            }
            ip[j] = v;
        }
#pragma unroll
        for (int j = 0; j < 5; j++) {
            int i = tid + j * 256;
            float v = 0.f;
            if (i < 1080) {
                int u = i % 40, tap = i / 40;
                v = wup[u * 270 + tap];
            }
            wpre[j] = v;
        }
#pragma unroll
        for (int j = 0; j < 4; j++) {
            int i = tid + j * 256;
            if (i < 972) { int dc = i / 324, rem = i % 324; sIn[0][dc][(rem/18)*19 + (rem%18)] = ip[j]; }
        }
#pragma unroll
        for (int j = 0; j < 5; j++) {
            int i = tid + j * 256;
            if (i < 1080) sW[0][i] = wpre[j];
        }
    }
    __syncthreads();

    int h = tid >> 4, w = tid & 15;
    unsigned long long acc[20];
#pragma unroll
    for (int j = 0; j < 20; j++) acc[j] = 0ULL;

#pragma unroll 1
    for (int t = 0; t < 10; t++) {
        int cur = t & 1;
        float ip[4], wpre[5];
        if (t < 9) {
            const float* inb2 = inb + (size_t)(t + 1) * (BBs * 768 * NP);
#pragma unroll
            for (int j = 0; j < 4; j++) {
                int i = tid + j * 256;
                float v = 0.f;
                if (i < 972) {
                    int dc = i / 324, rem = i % 324;
                    int hh = rem / 18, ww = rem % 18;
                    int ci = c + dc - 1;
                    int hy = hh - 1, wx = ww - 1;
                    if (ci >= 0 && ci < CCh && hy >= 0 && hy < 16 && wx >= 0 && wx < 16)
                        v = inb2[(size_t)ci * NP + hy * 16 + wx];
                }
                ip[j] = v;
            }
#pragma unroll
            for (int j = 0; j < 5; j++) {
                int i = tid + j * 256;
                float v = 0.f;
                if (i < 1080) {
                    int u = i % 40, tap = i / 40;
                    v = wup[u * 270 + (t + 1) * 27 + tap];
                }
                wpre[j] = v;
            }
        }

#pragma unroll
        for (int dc = 0; dc < 3; dc++) {
#pragma unroll
            for (int dh = 0; dh < 3; dh++) {
                const float* rowp = &sIn[cur][dc][(h + dh) * 19 + w];
#pragma unroll
                for (int dw = 0; dw < 3; dw++) {
                    unsigned long long vp; PACK2(vp, rowp[dw]);
                    const ulonglong2* wq = (const ulonglong2*)&sW[cur][((dc * 3 + dh) * 3 + dw) * 40];
#pragma unroll
                    for (int j = 0; j < 10; j++) {
                        ulonglong2 w2 = wq[j];
                        FMA2(acc[2 * j + 0], vp, w2.x);
                        FMA2(acc[2 * j + 1], vp, w2.y);
                    }
                }
            }
        }

        if (t < 9) {
            int nxt = cur ^ 1;
#pragma unroll
            for (int j = 0; j < 4; j++) {
                int i = tid + j * 256;
                if (i < 972) { int dc = i / 324, rem = i % 324; sIn[nxt][dc][(rem/18)*19 + (rem%18)] = ip[j]; }
            }
#pragma unroll
            for (int j = 0; j < 5; j++) {
                int i = tid + j * 256;
                if (i < 1080) sW[nxt][i] = wpre[j];
            }
        }
        __syncthreads();
    }

    float y[40];
#pragma unroll
    for (int j = 0; j < 20; j++) {
        unsigned lo, hi;
        UNPACK2(lo, hi, acc[j]);
        y[2 * j + 0] = __uint_as_float(lo);
        y[2 * j + 1] = __uint_as_float(hi);
    }
#pragma unroll
    for (int u = 0; u < 40; u++) y[u] = y[u] * sc[u] + sh[u];

    size_t ob = ((size_t)(br * 40) * BBs + b) * CCh * NP + (size_t)c * NP + tid;
#pragma unroll
    for (int r = 0; r < 4; r++) {
        float mem = 0.f;
#pragma unroll
        for (int s = 0; s < 10; s++) {
            int u = 4 * s + r;
            float xv = y[u];
            mem = mem + (xv - mem) * 0.5f;
            float spk = ((mem - 1.0f) > 0.f) ? 1.f : 0.f;
            out[ob + (size_t)u * (BBs * CCh * NP)] = spk;
            if (spk != 0.f) mem = 0.f;
        }
    }
}

// ---------------- TIM conv2 (grouped) + BN ----------------
__global__ void tim_conv2_kernel(const float* __restrict__ sp, const float* __restrict__ wdn,
                                 const float* __restrict__ sc, const float* __restrict__ sh,
                                 float* __restrict__ out)
{
    __shared__ float sW[108];
    __shared__ float sIn[12][18 * 19];
    int c  = blockIdx.x;
    int t  = blockIdx.y;
    int z  = blockIdx.z;
    int b  = z & 3;
    int br = z >> 2;
    int tid = threadIdx.x;

    if (tid < 108) sW[tid] = wdn[t * 108 + tid];
    for (int i = tid; i < 12 * 324; i += 256) {
        int pl = i / 324, rem = i % 324;
        int hh = rem / 18, ww = rem % 18;
        int r = pl / 3, dc = pl % 3;
        int u = t * 4 + r;
        int ci = c + dc - 1;
        int hy = hh - 1, wx = ww - 1;
        float v = 0.f;
        if (ci >= 0 && ci < CCh && hy >= 0 && hy < 16 && wx >= 0 && wx < 16)
            v = sp[(((size_t)(br * 40 + u) * BBs + b) * CCh + ci) * NP + hy * 16 + wx];
        sIn[pl][hh * 19 + ww] = v;
    }
    __syncthreads();

    int h = tid >> 4, w = tid & 15;
    float acc = 0.f;
#pragma unroll
    for (int r = 0; r < 4; r++) {
#pragma unroll
        for (int dc = 0; dc < 3; dc++) {
            const float* wr = &sW[r * 27 + dc * 9];
            const float* pp = &sIn[r * 3 + dc][0];
#pragma unroll
            for (int dh = 0; dh < 3; dh++) {
                const float* rp = &pp[(h + dh) * 19 + w];
                acc += rp[0] * wr[dh * 3 + 0];
                acc += rp[1] * wr[dh * 3 + 1];
                acc += rp[2] * wr[dh * 3 + 2];
            }
        }
    }
    out[(size_t)br * S_TBCN + (((size_t)t * BBs + b) * CCh + c) * NP + tid] = acc * sc[t] + sh[t];
}

// ---------------- LIF variants ----------------
__global__ void lif_kernel(const float* __restrict__ in, float* __restrict__ out,
                           int nChains, int stride, float vth)
{
    int i = blockIdx.x * blockDim.x + threadIdx.x;
    if (i >= nChains) return;
    float mem = 0.f;
    int p = i;
#pragma unroll
    for (int s = 0; s < 10; s++, p += stride) {
        float x = in[p];
        mem = mem + (x - mem) * 0.5f;
        float spk = ((mem - vth) > 0.f) ? 1.f : 0.f;
        out[p] = spk;
        if (spk != 0.f) mem = 0.f;
    }
}

__global__ void lif3_kernel(const float* __restrict__ in, float* __restrict__ out, float vth)
{
    int i = blockIdx.x * blockDim.x + threadIdx.x;
    if (i >= 3 * BCN) return;
    int br = i >> 18;
    int j  = i & (BCN - 1);
    size_t p = (size_t)br * S_TBCN + j;
    float mem = 0.f;
#pragma unroll
    for (int s = 0; s < 10; s++, p += BCN) {
        float x = in[p];
        mem = mem + (x - mem) * 0.5f;
        float spk = ((mem - vth) > 0.f) ? 1.f : 0.f;
        out[p] = spk;
        if (spk != 0.f) mem = 0.f;
    }
}

__global__ void lif_resid_kernel(const float* __restrict__ in, const float* __restrict__ res,
                                 float* __restrict__ out, int nChains, int stride, float vth)
{
    int i = blockIdx.x * blockDim.x + threadIdx.x;
    if (i >= nChains) return;
    float mem = 0.f;
    int p = i;
#pragma unroll
    for (int s = 0; s < 10; s++, p += stride) {
        float x = in[p];
        mem = mem + (x - mem) * 0.5f;
        float spk = ((mem - vth) > 0.f) ? 1.f : 0.f;
        out[p] = res[p] + spk;
        if (spk != 0.f) mem = 0.f;
    }
}

// ---------------- KtV ----------------
__global__ void ktv_kernel(const float* __restrict__ ks, const float* __restrict__ vs,
                           float* __restrict__ ktv)
{
    __shared__ float kT[16 * 257];
    __shared__ float vT[16 * 257];
    int tbh = blockIdx.x;
    int hh = tbh & 15;
    int tb = tbh >> 4;
    size_t base = ((size_t)tb * CCh + hh * 16) * NP;
    int tid = threadIdx.x;
    for (int i = tid; i < 16 * 256; i += 256) {
        int r = i >> 8, n = i & 255;
        kT[r * 257 + n] = ks[base + (size_t)r * NP + n];
        vT[r * 257 + n] = vs[base + (size_t)r * NP + n];
    }
    __syncthreads();
    int dd = tid >> 4, de = tid & 15;
    const float* kr = &kT[dd * 257];
    const float* vr = &vT[de * 257];
    float acc = 0.f;
#pragma unroll 8
    for (int n = 0; n < 256; n++) acc += kr[n] * vr[n];
    ktv[(size_t)tbh * 256 + dd * 16 + de] = acc;
}

// ---------------- attn out ----------------
__global__ void attn_o_kernel(const float* __restrict__ qs, const float* __restrict__ ktv,
                              float* __restrict__ o)
{
    __shared__ float sK[256];
    int tbh = blockIdx.x;
    int hh = tbh & 15;
    int tb = tbh >> 4;
    int tid = threadIdx.x;
    sK[tid] = ktv[(size_t)tbh * 256 + tid];
    __syncthreads();
    size_t base = ((size_t)tb * CCh + hh * 16) * NP + tid;
    float q[16];
#pragma unroll
    for (int d = 0; d < 16; d++) q[d] = qs[base + (size_t)d * NP];
#pragma unroll
    for (int dp = 0; dp < 16; dp++) {
        float acc = 0.f;
#pragma unroll
        for (int d = 0; d < 16; d++) acc += q[d] * sK[d * 16 + dp];
        o[base + (size_t)dp * NP] = acc * 0.25f;
    }
}

// ---------------- orchestration ----------------
extern "C" void kernel_launch(void* const* d_in, const int* in_sizes, int n_in,
                              void* d_out, int out_size)
{
    (void)in_sizes; (void)n_in; (void)out_size;
    const float* x        = (const float*)d_in[0];
    const float* q_w      = (const float*)d_in[1];
    const float* q_bn     = (const float*)d_in[2];
    const float* k_w      = (const float*)d_in[3];
    const float* k_bn     = (const float*)d_in[4];
    const float* v_w      = (const float*)d_in[5];
    const float* v_bn     = (const float*)d_in[6];
    const float* proj_w   = (const float*)d_in[7];
    const float* proj_bn  = (const float*)d_in[8];
    const float* tim_up_w = (const float*)d_in[9];
    const float* tim_bn1  = (const float*)d_in[10];
    const float* tim_dn_w = (const float*)d_in[11];
    const float* tim_bn2  = (const float*)d_in[12];
    const float* fc1_w    = (const float*)d_in[13];
    const float* fc1_b    = (const float*)d_in[14];
    const float* fc1_bn   = (const float*)d_in[15];
    const float* fc2_w    = (const float*)d_in[16];
    const float* fc2_b    = (const float*)d_in[17];
    const float* fc2_bn   = (const float*)d_in[18];
    float* outp = (float*)d_out;

    float *bufA, *bufB, *spk1, *spk2, *ybuf, *obuf, *hbuf, *ktvb;
    float *scal, *shif, *t1s, *t1h, *t2s, *t2h;
    __nv_bfloat16 *Aimg, *Bimg;
    cudaGetSymbolAddress((void**)&bufA, g_bufA);
    cudaGetSymbolAddress((void**)&bufB, g_bufB);
    cudaGetSymbolAddress((void**)&spk1, g_spk1);
    cudaGetSymbolAddress((void**)&spk2, g_spk2);
    cudaGetSymbolAddress((void**)&ybuf, g_y);
    cudaGetSymbolAddress((void**)&obuf, g_o);
    cudaGetSymbolAddress((void**)&hbuf, g_h);
    cudaGetSymbolAddress((void**)&ktvb, g_ktv);
    cudaGetSymbolAddress((void**)&scal, g_scale);
    cudaGetSymbolAddress((void**)&shif, g_shift);
    cudaGetSymbolAddress((void**)&t1s,  g_t1s);
    cudaGetSymbolAddress((void**)&t1h,  g_t1h);
    cudaGetSymbolAddress((void**)&t2s,  g_t2s);
    cudaGetSymbolAddress((void**)&t2h,  g_t2h);
    cudaGetSymbolAddress((void**)&Aimg, g_Aimg);
    cudaGetSymbolAddress((void**)&Bimg, g_Bimg);

    // ---- weight split images + BN folds ----
    w_prep_kernel<<<128, 256>>>(q_w,    Aimg + A_QKV, 256, 256, 6, 0);
    w_prep_kernel<<<128, 256>>>(k_w,    Aimg + A_QKV, 256, 256, 6, 2);
    w_prep_kernel<<<128, 256>>>(v_w,    Aimg + A_QKV, 256, 256, 6, 4);
    w_prep_kernel<<<128, 256>>>(proj_w, Aimg + A_PROJ, 256, 256, 2, 0);
    w_prep_kernel<<<512, 256>>>(fc1_w,  Aimg + A_FC1, 1024, 256, 8, 0);
    w_prep_kernel<<<512, 256>>>(fc2_w,  Aimg + A_FC2, 256, 1024, 2, 0);

    prep_bn_kernel<<<1, 256>>>(q_bn, nullptr, scal,       shif,       CCh);
    prep_bn_kernel<<<1, 256>>>(k_bn, nullptr, scal + 256, shif + 256, CCh);
    prep_bn_kernel<<<1, 256>>>(v_bn, nullptr, scal + 512, shif + 512, CCh);
    prep_bn_kernel<<<1, 256>>>(tim_bn1, nullptr, t1s, t1h, TRR);
    prep_bn_kernel<<<1, 256>>>(tim_bn2, nullptr, t2s, t2h, TT);

    // ---- qkv GEMM (6-term exact split) ----
    x3_prep_kernel<<<dim3(4, 4, 40), 256>>>(x, Bimg, 256);
    mma_gemm_kernel<<<dim3(6, 40), 512>>>(Aimg + A_QKV, Bimg, bufA, 768, 6, 4, 3, scal, shif);

    // ---- TIM ----
    tim_conv1_kernel<<<dim3(CCh, BBs, 3), 256>>>(bufA, tim_up_w, t1s, t1h, spk1);
    tim_conv2_kernel<<<dim3(CCh, TT, BBs*3), 256>>>(spk1, tim_dn_w, t2s, t2h, bufA);
    lif3_kernel<<<(3*BCN + 255)/256, 256>>>(bufA, spk2, 1.0f);

    // ---- attention (exact, binary) ----
    ktv_kernel<<<TT*BBs*16, 256>>>(spk2 + S_TBCN, spk2 + 2*S_TBCN, ktvb);
    attn_o_kernel<<<TT*BBs*16, 256>>>(spk2, ktvb, obuf);
    lif_kernel<<<(BCN + 255)/256, 256>>>(obuf, obuf, BCN, BCN, 0.5f);

    // ---- projection (binary input, 3-term exact) ----
    prep_bn_kernel<<<1, 256>>>(proj_bn, nullptr, scal, shif, CCh);
    x1_prep_kernel<<<dim3(4, 4, 40), 256>>>(obuf, Bimg, 256);
    mma_gemm_kernel<<<dim3(2, 40), 512>>>(Aimg + A_PROJ, Bimg, ybuf, 256, 2, 4, 1, scal, shif);
    lif_resid_kernel<<<(BCN + 255)/256, 256>>>(ybuf, x, hbuf, BCN, BCN, 1.0f);

    // ---- MLP fc1 (6-term exact split) ----
    prep_bn_kernel<<<(HIDD + 255)/256, 256>>>(fc1_bn, fc1_b, scal, shif, HIDD);
    x3_prep_kernel<<<dim3(4, 4, 40), 256>>>(hbuf, Bimg, 256);
    mma_gemm_kernel<<<dim3(8, 40), 512>>>(Aimg + A_FC1, Bimg, bufA, 1024, 8, 4, 3, scal, shif);
    lif_kernel<<<(BHN + 255)/256, 256>>>(bufA, bufB, BHN, BHN, 1.0f);

    // ---- MLP fc2 (binary input, 3-term exact) ----
    prep_bn_kernel<<<1, 256>>>(fc2_bn, fc2_b, scal, shif, CCh);
    x1_prep_kernel<<<dim3(16, 4, 40), 256>>>(bufB, Bimg, 1024);
    mma_gemm_kernel<<<dim3(2, 40), 512>>>(Aimg + A_FC2, Bimg, ybuf, 256, 2, 16, 1, scal, shif);
    lif_resid_kernel<<<(BCN + 255)/256, 256>>>(ybuf, hbuf, outp, BCN, BCN, 1.0f);
}

// round 10
// speedup vs baseline: 1.5394x; 1.5394x over previous
#include <cuda_runtime.h>
#include <math.h>

// ---------------- problem dims ----------------
#define TT    10
#define BBs   4
#define CCh   256
#define NP    256          // H*W = 16*16
#define TRR   40           // STEP*RATIO
#define HIDD  1024
#define EPSL  1e-5f

#define BCN   (BBs*CCh*NP)     // 262144 = 2^18
#define BHN   (BBs*HIDD*NP)    // 1048576
#define S_TBCN  (TT*BCN)       // 2,621,440
#define S_TRBCN (TRR*BBs*CCh*NP) // 10,485,760

// ---------------- scratch ----------------
__device__ float g_bufA[S_TRBCN];      // qkv gemm out / conv2 out / fc1 out
__device__ float g_bufB[S_TRBCN];      // fc1 spikes
__device__ float g_spk1[3*S_TRBCN];    // conv1 spikes, [br][u][b][c][n]
__device__ float g_spk2[3*S_TBCN];     // branch spikes, [br][t][b][c][n]
__device__ float g_y[S_TBCN];
__device__ float g_o[S_TBCN];
__device__ float g_h[S_TBCN];
__device__ float g_ktv[TT*BBs*16*256];
__device__ float g_wqkv[3*CCh*CCh];
__device__ float g_scale[HIDD];
__device__ float g_shift[HIDD];
__device__ float g_t1s[TRR], g_t1h[TRR];
__device__ float g_t2s[TT],  g_t2h[TT];

// ---------------- weight concat (q,k,v -> stacked O=768) ----------------
__global__ void concat3_kernel(const float* __restrict__ a, const float* __restrict__ b,
                               const float* __restrict__ c, float* __restrict__ dst, int n)
{
    int i = blockIdx.x * blockDim.x + threadIdx.x;
    if (i < n) dst[i] = a[i];
    else if (i < 2*n) dst[i] = b[i - n];
    else if (i < 3*n) dst[i] = c[i - 2*n];
}

// ---------------- BN folding ----------------
__global__ void prep_bn_kernel(const float* __restrict__ bnp, const float* __restrict__ bias,
                               float* __restrict__ scale, float* __restrict__ shift, int cnum)
{
    int i = blockIdx.x * blockDim.x + threadIdx.x;
    if (i >= cnum) return;
    float g  = bnp[i];
    float be = bnp[cnum + i];
    float m  = bnp[2*cnum + i];
    float v  = bnp[3*cnum + i];
    float s  = g / sqrtf(v + EPSL);
    float sh = be - m * s;
    if (bias) sh += bias[i] * s;
    scale[i] = s;
    shift[i] = sh;
}

// ---------------- batched GEMM + BN epilogue ----------------
// CTA tile 128(o) x 128(n), BK=8, 256 threads, microtile 16x4.
// warp w owns rows w*16..w*16+15; lane owns cols lane*4..lane*4+3.
// A-frag loads are warp-broadcast (free); B-frag is one conflict-free LDS.128.
#define APITCH 132
__global__ __launch_bounds__(256, 2)
void gemm_bn_kernel(const float* __restrict__ In, const float* __restrict__ Wm,
                    float* __restrict__ Out, int O, int K,
                    const float* __restrict__ scale, const float* __restrict__ shift)
{
    __shared__ __align__(16) float sA[2][8][APITCH];   // [buf][k][o] padded
    __shared__ __align__(16) float sB[2][8][128];      // [buf][k][n]
    int tb = blockIdx.z;
    int oBase = blockIdx.x * 128;
    int nBase = blockIdx.y * 128;
    const float* Bp = In + (size_t)tb * K * NP + nBase;
    float* Cp = Out + (size_t)tb * O * NP + nBase;
    int tid = threadIdx.x;
    int lane = tid & 31, warp = tid >> 5;

    int aro = tid >> 1, akq = (tid & 1) * 4;   // A: 128 rows x 2 k-quads
    int bk  = tid >> 5, bn  = (tid & 31) * 4;  // B: 8 k-rows x 32 n-quads

    const float* wp = &Wm[(size_t)(oBase + aro) * K + akq];
    const float* bp = &Bp[(size_t)bk * NP + bn];

    float4 av = *(const float4*)wp;
    float4 bv = *(const float4*)bp;
    sA[0][akq + 0][aro] = av.x; sA[0][akq + 1][aro] = av.y;
    sA[0][akq + 2][aro] = av.z; sA[0][akq + 3][aro] = av.w;
    *(float4*)&sB[0][bk][bn] = bv;
    __syncthreads();

    float acc[16][4];
#pragma unroll
    for (int i = 0; i < 16; i++)
#pragma unroll
        for (int j = 0; j < 4; j++) acc[i][j] = 0.f;

    int nk = K >> 3;
    for (int kt = 0; kt < nk; kt++) {
        int cur = kt & 1;
        if (kt + 1 < nk) {
            av = *(const float4*)(wp + (kt + 1) * 8);
            bv = *(const float4*)(bp + (size_t)(kt + 1) * 8 * NP);
        }
#pragma unroll
        for (int kk = 0; kk < 8; kk++) {
            float4 b  = *(const float4*)&sB[cur][kk][bn];        // bn == lane*4 for compute too
            float4 a0 = *(const float4*)&sA[cur][kk][warp * 16 + 0];
            float4 a1 = *(const float4*)&sA[cur][kk][warp * 16 + 4];
            float4 a2 = *(const float4*)&sA[cur][kk][warp * 16 + 8];
            float4 a3 = *(const float4*)&sA[cur][kk][warp * 16 + 12];
#define ROW(i, s) \
            acc[i][0] += (s) * b.x; acc[i][1] += (s) * b.y; \
            acc[i][2] += (s) * b.z; acc[i][3] += (s) * b.w;
            ROW(0, a0.x)  ROW(1, a0.y)  ROW(2, a0.z)  ROW(3, a0.w)
            ROW(4, a1.x)  ROW(5, a1.y)  ROW(6, a1.z)  ROW(7, a1.w)
            ROW(8, a2.x)  ROW(9, a2.y)  ROW(10, a2.z) ROW(11, a2.w)
            ROW(12, a3.x) ROW(13, a3.y) ROW(14, a3.z) ROW(15, a3.w)
#undef ROW
        }
        if (kt + 1 < nk) {
            int nxt = cur ^ 1;
            sA[nxt][akq + 0][aro] = av.x; sA[nxt][akq + 1][aro] = av.y;
            sA[nxt][akq + 2][aro] = av.z; sA[nxt][akq + 3][aro] = av.w;
            *(float4*)&sB[nxt][bk][bn] = bv;
        }
        __syncthreads();
    }

#pragma unroll
    for (int i = 0; i < 16; i++) {
        int o = oBase + warp * 16 + i;
        float sc = scale[o], sh = shift[o];
        float4 r;
        r.x = acc[i][0] * sc + sh; r.y = acc[i][1] * sc + sh;
        r.z = acc[i][2] * sc + sh; r.w = acc[i][3] * sc + sh;
        *(float4*)&Cp[(size_t)o * NP + lane * 4] = r;
    }
}

// ---------------- TIM conv1 + BN + fused LIF1, t-staged, all branches ----------------
// in : stacked qkv gemm out, index ((t*B + b)*768 + br*256 + ci)*256 + n
// out: spikes, index ((br*40 + u)*B + b)*C*N + c*N + n
__global__ __launch_bounds__(256)
void tim_conv1_kernel(const float* __restrict__ in, const float* __restrict__ wup,
                      const float* __restrict__ sc, const float* __restrict__ sh,
                      float* __restrict__ out)
{
    __shared__ __align__(16) float sW[2][1080];       // [tap(27)][u(40)]
    __shared__ float sIn[2][3][18*19];                // [dc][18 rows x pitch 19]
    int c  = blockIdx.x;
    int b  = blockIdx.y;
    int br = blockIdx.z;
    int tid = threadIdx.x;
    const float* inb = in + ((size_t)b * 768 + br * 256) * NP;

    // ---- prologue: stage t=0 into buffer 0 ----
    {
        float ip[4], wpre[5];
#pragma unroll
        for (int j = 0; j < 4; j++) {
            int i = tid + j * 256;
            float v = 0.f;
            if (i < 972) {
                int dc = i / 324, rem = i % 324;
                int hh = rem / 18, ww = rem % 18;
                int ci = c + dc - 1;
                int hy = hh - 1, wx = ww - 1;
                if (ci >= 0 && ci < CCh && hy >= 0 && hy < 16 && wx >= 0 && wx < 16)
                    v = inb[(size_t)ci * NP + hy * 16 + wx];
            }
            ip[j] = v;
        }
#pragma unroll
        for (int j = 0; j < 5; j++) {
            int i = tid + j * 256;
            float v = 0.f;
            if (i < 1080) {
                int u = i % 40, tap = i / 40;
                v = wup[u * 270 + tap];          // t=0
            }
            wpre[j] = v;
        }
#pragma unroll
        for (int j = 0; j < 4; j++) {
            int i = tid + j * 256;
            if (i < 972) { int dc = i / 324, rem = i % 324; sIn[0][dc][(rem/18)*19 + (rem%18)] = ip[j]; }
        }
#pragma unroll
        for (int j = 0; j < 5; j++) {
            int i = tid + j * 256;
            if (i < 1080) sW[0][i] = wpre[j];
        }
    }
    __syncthreads();

    int h = tid >> 4, w = tid & 15;
    float acc[40];
#pragma unroll
    for (int u = 0; u < 40; u++) acc[u] = 0.f;

#pragma unroll 1
    for (int t = 0; t < 10; t++) {
        int cur = t & 1;
        float ip[4], wpre[5];
        if (t < 9) {
            const float* inb2 = inb + (size_t)(t + 1) * (BBs * 768 * NP);
#pragma unroll
            for (int j = 0; j < 4; j++) {
                int i = tid + j * 256;
                float v = 0.f;
                if (i < 972) {
                    int dc = i / 324, rem = i % 324;
                    int hh = rem / 18, ww = rem % 18;
                    int ci = c + dc - 1;
                    int hy = hh - 1, wx = ww - 1;
                    if (ci >= 0 && ci < CCh && hy >= 0 && hy < 16 && wx >= 0 && wx < 16)
                        v = inb2[(size_t)ci * NP + hy * 16 + wx];
                }
                ip[j] = v;
            }
#pragma unroll
            for (int j = 0; j < 5; j++) {
                int i = tid + j * 256;
                float v = 0.f;
                if (i < 1080) {
                    int u = i % 40, tap = i / 40;
                    v = wup[u * 270 + (t + 1) * 27 + tap];
                }
                wpre[j] = v;
            }
        }

        // ---- compute t from buffer cur (scalar FFMA, float4 weight fetch) ----
#pragma unroll
        for (int dc = 0; dc < 3; dc++) {
#pragma unroll
            for (int dh = 0; dh < 3; dh++) {
                const float* rowp = &sIn[cur][dc][(h + dh) * 19 + w];
#pragma unroll
                for (int dw = 0; dw < 3; dw++) {
                    float v = rowp[dw];
                    const float4* wq = (const float4*)&sW[cur][((dc * 3 + dh) * 3 + dw) * 40];
#pragma unroll
                    for (int j = 0; j < 10; j++) {
                        float4 w4 = wq[j];
                        acc[4 * j + 0] += v * w4.x;
                        acc[4 * j + 1] += v * w4.y;
                        acc[4 * j + 2] += v * w4.z;
                        acc[4 * j + 3] += v * w4.w;
                    }
                }
            }
        }

        if (t < 9) {
            int nxt = cur ^ 1;
#pragma unroll
            for (int j = 0; j < 4; j++) {
                int i = tid + j * 256;
                if (i < 972) { int dc = i / 324, rem = i % 324; sIn[nxt][dc][(rem/18)*19 + (rem%18)] = ip[j]; }
            }
#pragma unroll
            for (int j = 0; j < 5; j++) {
                int i = tid + j * 256;
                if (i < 1080) sW[nxt][i] = wpre[j];
            }
        }
        __syncthreads();
    }

    // ---- BN + fused LIF1 epilogue ----
    float y[40];
#pragma unroll
    for (int u = 0; u < 40; u++) y[u] = acc[u] * sc[u] + sh[u];

    size_t ob = ((size_t)(br * 40) * BBs + b) * CCh * NP + (size_t)c * NP + tid;
#pragma unroll
    for (int r = 0; r < 4; r++) {
        float mem = 0.f;
#pragma unroll
        for (int s = 0; s < 10; s++) {
            int u = 4 * s + r;
            float xv = y[u];
            mem = mem + (xv - mem) * 0.5f;
            float spk = ((mem - 1.0f) > 0.f) ? 1.f : 0.f;
            out[ob + (size_t)u * (BBs * CCh * NP)] = spk;
            if (spk != 0.f) mem = 0.f;
        }
    }
}

// ---------------- TIM conv2 (grouped) + BN, smem-staged, all branches ----------------
// sp : spikes [br][u][b][c][n];  out: [br][t][b][c][n] (pre-LIF values)
__global__ void tim_conv2_kernel(const float* __restrict__ sp, const float* __restrict__ wdn,
                                 const float* __restrict__ sc, const float* __restrict__ sh,
                                 float* __restrict__ out)
{
    __shared__ float sW[108];
    __shared__ float sIn[12][18 * 19];     // [r*3+dc][padded]
    int c  = blockIdx.x;
    int t  = blockIdx.y;
    int z  = blockIdx.z;
    int b  = z & 3;
    int br = z >> 2;
    int tid = threadIdx.x;

    if (tid < 108) sW[tid] = wdn[t * 108 + tid];
    for (int i = tid; i < 12 * 324; i += 256) {
        int pl = i / 324, rem = i % 324;
        int hh = rem / 18, ww = rem % 18;
        int r = pl / 3, dc = pl % 3;
        int u = t * 4 + r;
        int ci = c + dc - 1;
        int hy = hh - 1, wx = ww - 1;
        float v = 0.f;
        if (ci >= 0 && ci < CCh && hy >= 0 && hy < 16 && wx >= 0 && wx < 16)
            v = sp[(((size_t)(br * 40 + u) * BBs + b) * CCh + ci) * NP + hy * 16 + wx];
        sIn[pl][hh * 19 + ww] = v;
    }
    __syncthreads();

    int h = tid >> 4, w = tid & 15;
    float acc = 0.f;
#pragma unroll
    for (int r = 0; r < 4; r++) {
#pragma unroll
        for (int dc = 0; dc < 3; dc++) {
            const float* wr = &sW[r * 27 + dc * 9];
            const float* pp = &sIn[r * 3 + dc][0];
#pragma unroll
            for (int dh = 0; dh < 3; dh++) {
                const float* rp = &pp[(h + dh) * 19 + w];
                acc += rp[0] * wr[dh * 3 + 0];
                acc += rp[1] * wr[dh * 3 + 1];
                acc += rp[2] * wr[dh * 3 + 2];
            }
        }
    }
    out[(size_t)br * S_TBCN + (((size_t)t * BBs + b) * CCh + c) * NP + tid] = acc * sc[t] + sh[t];
}

// ---------------- LIF variants ----------------
__global__ void lif_kernel(const float* __restrict__ in, float* __restrict__ out,
                           int nChains, int stride, float vth)
{
    int i = blockIdx.x * blockDim.x + threadIdx.x;
    if (i >= nChains) return;
    float mem = 0.f;
    int p = i;
#pragma unroll
    for (int s = 0; s < 10; s++, p += stride) {
        float x = in[p];
        mem = mem + (x - mem) * 0.5f;
        float spk = ((mem - vth) > 0.f) ? 1.f : 0.f;
        out[p] = spk;
        if (spk != 0.f) mem = 0.f;
    }
}

// merged 3-branch lif: in/out laid out [br][t][b][c][n]
__global__ void lif3_kernel(const float* __restrict__ in, float* __restrict__ out, float vth)
{
    int i = blockIdx.x * blockDim.x + threadIdx.x;
    if (i >= 3 * BCN) return;
    int br = i >> 18;
    int j  = i & (BCN - 1);
    size_t p = (size_t)br * S_TBCN + j;
    float mem = 0.f;
#pragma unroll
    for (int s = 0; s < 10; s++, p += BCN) {
        float x = in[p];
        mem = mem + (x - mem) * 0.5f;
        float spk = ((mem - vth) > 0.f) ? 1.f : 0.f;
        out[p] = spk;
        if (spk != 0.f) mem = 0.f;
    }
}

__global__ void lif_resid_kernel(const float* __restrict__ in, const float* __restrict__ res,
                                 float* __restrict__ out, int nChains, int stride, float vth)
{
    int i = blockIdx.x * blockDim.x + threadIdx.x;
    if (i >= nChains) return;
    float mem = 0.f;
    int p = i;
#pragma unroll
    for (int s = 0; s < 10; s++, p += stride) {
        float x = in[p];
        mem = mem + (x - mem) * 0.5f;
        float spk = ((mem - vth) > 0.f) ? 1.f : 0.f;
        out[p] = res[p] + spk;
        if (spk != 0.f) mem = 0.f;
    }
}

// ---------------- KtV: per (t,b,head): 16x16 Gram over N ----------------
__global__ void ktv_kernel(const float* __restrict__ ks, const float* __restrict__ vs,
                           float* __restrict__ ktv)
{
    __shared__ float kT[16 * 257];
    __shared__ float vT[16 * 257];
    int tbh = blockIdx.x;
    int hh = tbh & 15;
    int tb = tbh >> 4;
    size_t base = ((size_t)tb * CCh + hh * 16) * NP;
    int tid = threadIdx.x;
    for (int i = tid; i < 16 * 256; i += 256) {
        int r = i >> 8, n = i & 255;
        kT[r * 257 + n] = ks[base + (size_t)r * NP + n];
        vT[r * 257 + n] = vs[base + (size_t)r * NP + n];
    }
    __syncthreads();
    int dd = tid >> 4, de = tid & 15;
    const float* kr = &kT[dd * 257];
    const float* vr = &vT[de * 257];
    float acc = 0.f;
#pragma unroll 8
    for (int n = 0; n < 256; n++) acc += kr[n] * vr[n];
    ktv[(size_t)tbh * 256 + dd * 16 + de] = acc;
}

// ---------------- attn out: o = 0.25 * Q (KtV) ----------------
__global__ void attn_o_kernel(const float* __restrict__ qs, const float* __restrict__ ktv,
                              float* __restrict__ o)
{
    __shared__ float sK[256];
    int tbh = blockIdx.x;
    int hh = tbh & 15;
    int tb = tbh >> 4;
    int tid = threadIdx.x;
    sK[tid] = ktv[(size_t)tbh * 256 + tid];
    __syncthreads();
    size_t base = ((size_t)tb * CCh + hh * 16) * NP + tid;
    float q[16];
#pragma unroll
    for (int d = 0; d < 16; d++) q[d] = qs[base + (size_t)d * NP];
#pragma unroll
    for (int dp = 0; dp < 16; dp++) {
        float acc = 0.f;
#pragma unroll
        for (int d = 0; d < 16; d++) acc += q[d] * sK[d * 16 + dp];
        o[base + (size_t)dp * NP] = acc * 0.25f;
    }
}

// ---------------- orchestration ----------------
extern "C" void kernel_launch(void* const* d_in, const int* in_sizes, int n_in,
                              void* d_out, int out_size)
{
    (void)in_sizes; (void)n_in; (void)out_size;
    const float* x        = (const float*)d_in[0];
    const float* q_w      = (const float*)d_in[1];
    const float* q_bn     = (const float*)d_in[2];
    const float* k_w      = (const float*)d_in[3];
    const float* k_bn     = (const float*)d_in[4];
    const float* v_w      = (const float*)d_in[5];
    const float* v_bn     = (const float*)d_in[6];
    const float* proj_w   = (const float*)d_in[7];
    const float* proj_bn  = (const float*)d_in[8];
    const float* tim_up_w = (const float*)d_in[9];
    const float* tim_bn1  = (const float*)d_in[10];
    const float* tim_dn_w = (const float*)d_in[11];
    const float* tim_bn2  = (const float*)d_in[12];
    const float* fc1_w    = (const float*)d_in[13];
    const float* fc1_b    = (const float*)d_in[14];
    const float* fc1_bn   = (const float*)d_in[15];
    const float* fc2_w    = (const float*)d_in[16];
    const float* fc2_b    = (const float*)d_in[17];
    const float* fc2_bn   = (const float*)d_in[18];
    float* outp = (float*)d_out;

    float *bufA, *bufB, *spk1, *spk2, *ybuf, *obuf, *hbuf, *ktvb, *wqkv;
    float *scal, *shif, *t1s, *t1h, *t2s, *t2h;
    cudaGetSymbolAddress((void**)&bufA, g_bufA);
    cudaGetSymbolAddress((void**)&bufB, g_bufB);
    cudaGetSymbolAddress((void**)&spk1, g_spk1);
    cudaGetSymbolAddress((void**)&spk2, g_spk2);
    cudaGetSymbolAddress((void**)&ybuf, g_y);
    cudaGetSymbolAddress((void**)&obuf, g_o);
    cudaGetSymbolAddress((void**)&hbuf, g_h);
    cudaGetSymbolAddress((void**)&ktvb, g_ktv);
    cudaGetSymbolAddress((void**)&wqkv, g_wqkv);
    cudaGetSymbolAddress((void**)&scal, g_scale);
    cudaGetSymbolAddress((void**)&shif, g_shift);
    cudaGetSymbolAddress((void**)&t1s,  g_t1s);
    cudaGetSymbolAddress((void**)&t1h,  g_t1h);
    cudaGetSymbolAddress((void**)&t2s,  g_t2s);
    cudaGetSymbolAddress((void**)&t2h,  g_t2h);

    // weight concat + BN folds
    concat3_kernel<<<768, 256>>>(q_w, k_w, v_w, wqkv, CCh * CCh);
    prep_bn_kernel<<<1, 256>>>(q_bn, nullptr, scal,        shif,        CCh);
    prep_bn_kernel<<<1, 256>>>(k_bn, nullptr, scal + 256,  shif + 256,  CCh);
    prep_bn_kernel<<<1, 256>>>(v_bn, nullptr, scal + 512,  shif + 512,  CCh);
    prep_bn_kernel<<<1, 256>>>(tim_bn1, nullptr, t1s, t1h, TRR);
    prep_bn_kernel<<<1, 256>>>(tim_bn2, nullptr, t2s, t2h, TT);

    // merged q/k/v GEMM: Out (tb, 768, n)
    gemm_bn_kernel<<<dim3(6, 2, TT*BBs), 256>>>(x, wqkv, bufA, 768, CCh, scal, shif);

    // TIM: conv1 + BN + LIF1 (all branches), conv2 + BN, LIF2
    tim_conv1_kernel<<<dim3(CCh, BBs, 3), 256>>>(bufA, tim_up_w, t1s, t1h, spk1);
    tim_conv2_kernel<<<dim3(CCh, TT, BBs*3), 256>>>(spk1, tim_dn_w, t2s, t2h, bufA);
    lif3_kernel<<<(3*BCN + 255)/256, 256>>>(bufA, spk2, 1.0f);

    // attention (linear, binary, exact): q=br0, k=br1, v=br2
    ktv_kernel<<<TT*BBs*16, 256>>>(spk2 + S_TBCN, spk2 + 2*S_TBCN, ktvb);
    attn_o_kernel<<<TT*BBs*16, 256>>>(spk2, ktvb, obuf);
    lif_kernel<<<(BCN + 255)/256, 256>>>(obuf, obuf, BCN, BCN, 0.5f);

    // projection + BN + lif; residual h = x + spikes
    prep_bn_kernel<<<1, 256>>>(proj_bn, nullptr, scal, shif, CCh);
    gemm_bn_kernel<<<dim3(2, 2, TT*BBs), 256>>>(obuf, proj_w, ybuf, CCh, CCh, scal, shif);
    lif_resid_kernel<<<(BCN + 255)/256, 256>>>(ybuf, x, hbuf, BCN, BCN, 1.0f);

    // MLP
    prep_bn_kernel<<<(HIDD + 255)/256, 256>>>(fc1_bn, fc1_b, scal, shif, HIDD);
    gemm_bn_kernel<<<dim3(8, 2, TT*BBs), 256>>>(hbuf, fc1_w, bufA, HIDD, CCh, scal, shif);
    lif_kernel<<<(BHN + 255)/256, 256>>>(bufA, bufB, BHN, BHN, 1.0f);

    prep_bn_kernel<<<1, 256>>>(fc2_bn, fc2_b, scal, shif, CCh);
    gemm_bn_kernel<<<dim3(2, 2, TT*BBs), 256>>>(bufB, fc2_w, ybuf, CCh, HIDD, scal, shif);
    lif_resid_kernel<<<(BCN + 255)/256, 256>>>(ybuf, hbuf, outp, BCN, BCN, 1.0f);
}

// round 13
// speedup vs baseline: 1.7016x; 1.1054x over previous
#include <cuda_runtime.h>
#include <math.h>

// ---------------- problem dims ----------------
#define TT    10
#define BBs   4
#define CCh   256
#define NP    256          // H*W = 16*16
#define TRR   40           // STEP*RATIO
#define HIDD  1024
#define EPSL  1e-5f

#define BCN   (BBs*CCh*NP)     // 262144 = 2^18
#define BHN   (BBs*HIDD*NP)    // 1048576
#define S_TBCN  (TT*BCN)       // 2,621,440
#define S_TRBCN (TRR*BBs*CCh*NP) // 10,485,760

// ---------------- scratch ----------------
__device__ float g_bufA[S_TRBCN];      // qkv gemm out / fc1 out
__device__ float g_bufB[S_TRBCN];      // fc1 spikes
__device__ float g_spk1[3*S_TRBCN];    // conv1 spikes, [br][u][b][c][n]
__device__ float g_spk2[3*S_TBCN];     // branch spikes, [br][t][b][c][n]
__device__ float g_y[S_TBCN];
__device__ float g_o[S_TBCN];
__device__ float g_h[S_TBCN];
__device__ float g_ktv[TT*BBs*16*256];
__device__ float g_wqkv[3*CCh*CCh];
__device__ float g_scale[2560];
__device__ float g_shift[2560];
__device__ float g_t1s[TRR], g_t1h[TRR];
__device__ float g_t2s[TT],  g_t2h[TT];

// scale/shift slice offsets
#define SC_QKV  0
#define SC_PROJ 768
#define SC_FC1  1024
#define SC_FC2  2048

// ---------------- merged prep: wqkv concat + ALL BN folds in one launch ----------------
__device__ __forceinline__ void fold_one(const float* __restrict__ bnp, const float* __restrict__ bias,
                                         int cnum, int i, float* __restrict__ s_, float* __restrict__ h_)
{
    if (i >= cnum) return;
    float g  = bnp[i];
    float be = bnp[cnum + i];
    float m  = bnp[2*cnum + i];
    float v  = bnp[3*cnum + i];
    float s  = g / sqrtf(v + EPSL);
    float sh = be - m * s;
    if (bias) sh += bias[i] * s;
    s_[i] = s;
    h_[i] = sh;
}

__global__ void prep_all_kernel(
    const float* __restrict__ qw, const float* __restrict__ kw, const float* __restrict__ vw,
    float* __restrict__ wqkv,
    const float* __restrict__ qbn, const float* __restrict__ kbn, const float* __restrict__ vbn,
    const float* __restrict__ projbn,
    const float* __restrict__ fc1bn, const float* __restrict__ fc1b,
    const float* __restrict__ fc2bn, const float* __restrict__ fc2b,
    const float* __restrict__ t1bn, const float* __restrict__ t2bn,
    float* __restrict__ scal, float* __restrict__ shif,
    float* __restrict__ t1s, float* __restrict__ t1h,
    float* __restrict__ t2s, float* __restrict__ t2h)
{
    int bx = blockIdx.x, tid = threadIdx.x;
    if (bx < 768) {
        int i = bx * 256 + tid;
        const int n = CCh * CCh;
        float v = (i < n) ? qw[i] : (i < 2*n) ? kw[i - n] : vw[i - 2*n];
        wqkv[i] = v;
        return;
    }
    int job = bx - 768;
    switch (job) {
        case 0:  fold_one(qbn,    nullptr, 256,  tid, scal + SC_QKV,       shif + SC_QKV);       break;
        case 1:  fold_one(kbn,    nullptr, 256,  tid, scal + SC_QKV + 256, shif + SC_QKV + 256); break;
        case 2:  fold_one(vbn,    nullptr, 256,  tid, scal + SC_QKV + 512, shif + SC_QKV + 512); break;
        case 3:  fold_one(projbn, nullptr, 256,  tid, scal + SC_PROJ,      shif + SC_PROJ);      break;
        case 4: case 5: case 6: case 7:
                 fold_one(fc1bn,  fc1b,    1024, (job - 4) * 256 + tid, scal + SC_FC1, shif + SC_FC1); break;
        case 8:  fold_one(fc2bn,  fc2b,    256,  tid, scal + SC_FC2,       shif + SC_FC2);       break;
        case 9:  fold_one(t1bn,   nullptr, TRR,  tid, t1s, t1h); break;
        case 10: fold_one(t2bn,   nullptr, TT,   tid, t2s, t2h); break;
    }
}

// ---------------- batched GEMM + BN epilogue ----------------
// CTA tile 128(o) x 128(n), BK=8, 256 threads, microtile 16x4.
#define APITCH 132
__global__ __launch_bounds__(256, 2)
void gemm_bn_kernel(const float* __restrict__ In, const float* __restrict__ Wm,
                    float* __restrict__ Out, int O, int K,
                    const float* __restrict__ scale, const float* __restrict__ shift)
{
    __shared__ __align__(16) float sA[2][8][APITCH];   // [buf][k][o] padded
    __shared__ __align__(16) float sB[2][8][128];      // [buf][k][n]
    int tb = blockIdx.z;
    int oBase = blockIdx.x * 128;
    int nBase = blockIdx.y * 128;
    const float* Bp = In + (size_t)tb * K * NP + nBase;
    float* Cp = Out + (size_t)tb * O * NP + nBase;
    int tid = threadIdx.x;
    int lane = tid & 31, warp = tid >> 5;

    int aro = tid >> 1, akq = (tid & 1) * 4;
    int bk  = tid >> 5, bn  = (tid & 31) * 4;

    const float* wp = &Wm[(size_t)(oBase + aro) * K + akq];
    const float* bp = &Bp[(size_t)bk * NP + bn];

    float4 av = *(const float4*)wp;
    float4 bv = *(const float4*)bp;
    sA[0][akq + 0][aro] = av.x; sA[0][akq + 1][aro] = av.y;
    sA[0][akq + 2][aro] = av.z; sA[0][akq + 3][aro] = av.w;
    *(float4*)&sB[0][bk][bn] = bv;
    __syncthreads();

    float acc[16][4];
#pragma unroll
    for (int i = 0; i < 16; i++)
#pragma unroll
        for (int j = 0; j < 4; j++) acc[i][j] = 0.f;

    int nk = K >> 3;
    for (int kt = 0; kt < nk; kt++) {
        int cur = kt & 1;
        if (kt + 1 < nk) {
            av = *(const float4*)(wp + (kt + 1) * 8);
            bv = *(const float4*)(bp + (size_t)(kt + 1) * 8 * NP);
        }
#pragma unroll
        for (int kk = 0; kk < 8; kk++) {
            float4 b  = *(const float4*)&sB[cur][kk][bn];
            float4 a0 = *(const float4*)&sA[cur][kk][warp * 16 + 0];
            float4 a1 = *(const float4*)&sA[cur][kk][warp * 16 + 4];
            float4 a2 = *(const float4*)&sA[cur][kk][warp * 16 + 8];
            float4 a3 = *(const float4*)&sA[cur][kk][warp * 16 + 12];
#define ROW(i, s) \
            acc[i][0] += (s) * b.x; acc[i][1] += (s) * b.y; \
            acc[i][2] += (s) * b.z; acc[i][3] += (s) * b.w;
            ROW(0, a0.x)  ROW(1, a0.y)  ROW(2, a0.z)  ROW(3, a0.w)
            ROW(4, a1.x)  ROW(5, a1.y)  ROW(6, a1.z)  ROW(7, a1.w)
            ROW(8, a2.x)  ROW(9, a2.y)  ROW(10, a2.z) ROW(11, a2.w)
            ROW(12, a3.x) ROW(13, a3.y) ROW(14, a3.z) ROW(15, a3.w)
#undef ROW
        }
        if (kt + 1 < nk) {
            int nxt = cur ^ 1;
            sA[nxt][akq + 0][aro] = av.x; sA[nxt][akq + 1][aro] = av.y;
            sA[nxt][akq + 2][aro] = av.z; sA[nxt][akq + 3][aro] = av.w;
            *(float4*)&sB[nxt][bk][bn] = bv;
        }
        __syncthreads();
    }

#pragma unroll
    for (int i = 0; i < 16; i++) {
        int o = oBase + warp * 16 + i;
        float sc = scale[o], sh = shift[o];
        float4 r;
        r.x = acc[i][0] * sc + sh; r.y = acc[i][1] * sc + sh;
        r.z = acc[i][2] * sc + sh; r.w = acc[i][3] * sc + sh;
        *(float4*)&Cp[(size_t)o * NP + lane * 4] = r;
    }
}

// ---------------- TIM conv1 + BN + fused LIF1, pixel-pair microtile ----------------
// Thread: uh = tid>>7 selects 20 u's = chains r in {2uh, 2uh+1}; pp = tid&127 selects pixel pair.
// Weight smem permuted: sW[tap*40 + pos(u)], pos(u) = (r>>1)*20 + s*2 + (r&1), u = 4s+r.
__global__ __launch_bounds__(256)
void tim_conv1_kernel(const float* __restrict__ in, const float* __restrict__ wup,
                      const float* __restrict__ sc, const float* __restrict__ sh,
                      float* __restrict__ out)
{
    __shared__ __align__(16) float sW[2][1080];
    __shared__ float sIn[2][3][18*19];
    __shared__ float sSc[40], sSh[40];
    int c  = blockIdx.x;
    int b  = blockIdx.y;
    int br = blockIdx.z;
    int tid = threadIdx.x;
    const float* inb = in + ((size_t)b * 768 + br * 256) * NP;

    if (tid < 40) { sSc[tid] = sc[tid]; sSh[tid] = sh[tid]; }

    // ---- prologue: stage t=0 ----
    {
        float ip[4], wpre[5];
#pragma unroll
        for (int j = 0; j < 4; j++) {
            int i = tid + j * 256;
            float v = 0.f;
            if (i < 972) {
                int dc = i / 324, rem = i % 324;
                int hh = rem / 18, ww = rem % 18;
                int ci = c + dc - 1;
                int hy = hh - 1, wx = ww - 1;
                if (ci >= 0 && ci < CCh && hy >= 0 && hy < 16 && wx >= 0 && wx < 16)
                    v = inb[(size_t)ci * NP + hy * 16 + wx];
            }
            ip[j] = v;
        }
#pragma unroll
        for (int j = 0; j < 5; j++) {
            int i = tid + j * 256;
            float v = 0.f;
            if (i < 1080) {
                int u = i % 40, tap = i / 40;
                v = wup[u * 270 + tap];
            }
            wpre[j] = v;
        }
#pragma unroll
        for (int j = 0; j < 4; j++) {
            int i = tid + j * 256;
            if (i < 972) { int dc = i / 324, rem = i % 324; sIn[0][dc][(rem/18)*19 + (rem%18)] = ip[j]; }
        }
#pragma unroll
        for (int j = 0; j < 5; j++) {
            int i = tid + j * 256;
            if (i < 1080) {
                int u = i % 40, tap = i / 40;
                int pos = ((u & 3) >> 1) * 20 + (u >> 2) * 2 + (u & 1);
                sW[0][tap * 40 + pos] = wpre[j];
            }
        }
    }
    __syncthreads();

    int uh = tid >> 7;            // 0/1: which 20-u half
    int pp = tid & 127;           // pixel pair index
    int h = pp >> 3, w0 = (pp & 7) * 2;

    float acc[2][20];
#pragma unroll
    for (int px = 0; px < 2; px++)
#pragma unroll
        for (int j = 0; j < 20; j++) acc[px][j] = 0.f;

#pragma unroll 1
    for (int t = 0; t < 10; t++) {
        int cur = t & 1;
        float ip[4], wpre[5];
        if (t < 9) {
            const float* inb2 = inb + (size_t)(t + 1) * (BBs * 768 * NP);
#pragma unroll
            for (int j = 0; j < 4; j++) {
                int i = tid + j * 256;
                float v = 0.f;
                if (i < 972) {
                    int dc = i / 324, rem = i % 324;
                    int hh = rem / 18, ww = rem % 18;
                    int ci = c + dc - 1;
                    int hy = hh - 1, wx = ww - 1;
                    if (ci >= 0 && ci < CCh && hy >= 0 && hy < 16 && wx >= 0 && wx < 16)
                        v = inb2[(size_t)ci * NP + hy * 16 + wx];
                }
                ip[j] = v;
            }
#pragma unroll
            for (int j = 0; j < 5; j++) {
                int i = tid + j * 256;
                float v = 0.f;
                if (i < 1080) {
                    int u = i % 40, tap = i / 40;
                    v = wup[u * 270 + (t + 1) * 27 + tap];
                }
                wpre[j] = v;
            }
        }

        // ---- compute t ----
#pragma unroll
        for (int dc = 0; dc < 3; dc++) {
#pragma unroll
            for (int dh = 0; dh < 3; dh++) {
                const float* rowp = &sIn[cur][dc][(h + dh) * 19 + w0];
                float inp0 = rowp[0], inp1 = rowp[1], inp2 = rowp[2], inp3 = rowp[3];
                float iv[4] = {inp0, inp1, inp2, inp3};
#pragma unroll
                for (int dw = 0; dw < 3; dw++) {
                    float v0 = iv[dw], v1 = iv[dw + 1];
                    const float4* wq = (const float4*)&sW[cur][((dc * 3 + dh) * 3 + dw) * 40 + uh * 20];
#pragma unroll
                    for (int j = 0; j < 5; j++) {
                        float4 w4 = wq[j];
                        acc[0][4*j + 0] += v0 * w4.x; acc[1][4*j + 0] += v1 * w4.x;
                        acc[0][4*j + 1] += v0 * w4.y; acc[1][4*j + 1] += v1 * w4.y;
                        acc[0][4*j + 2] += v0 * w4.z; acc[1][4*j + 2] += v1 * w4.z;
                        acc[0][4*j + 3] += v0 * w4.w; acc[1][4*j + 3] += v1 * w4.w;
                    }
                }
            }
        }

        if (t < 9) {
            int nxt = cur ^ 1;
#pragma unroll
            for (int j = 0; j < 4; j++) {
                int i = tid + j * 256;
                if (i < 972) { int dc = i / 324, rem = i % 324; sIn[nxt][dc][(rem/18)*19 + (rem%18)] = ip[j]; }
            }
#pragma unroll
            for (int j = 0; j < 5; j++) {
                int i = tid + j * 256;
                if (i < 1080) {
                    int u = i % 40, tap = i / 40;
                    int pos = ((u & 3) >> 1) * 20 + (u >> 2) * 2 + (u & 1);
                    sW[nxt][tap * 40 + pos] = wpre[j];
                }
            }
        }
        __syncthreads();
    }

    // ---- BN + fused LIF1 epilogue (chains r = 2uh + r01) ----
    size_t ob = ((size_t)(br * 40) * BBs + b) * CCh * NP + (size_t)c * NP + 2 * pp;
#pragma unroll
    for (int r01 = 0; r01 < 2; r01++) {
        int r = 2 * uh + r01;
        float mem0 = 0.f, mem1 = 0.f;
#pragma unroll
        for (int s = 0; s < 10; s++) {
            int u = 4 * s + r;
            int j = 2 * s + r01;
            float y0 = acc[0][j] * sSc[u] + sSh[u];
            float y1 = acc[1][j] * sSc[u] + sSh[u];
            mem0 = mem0 + (y0 - mem0) * 0.5f;
            mem1 = mem1 + (y1 - mem1) * 0.5f;
            float s0 = ((mem0 - 1.0f) > 0.f) ? 1.f : 0.f;
            float s1 = ((mem1 - 1.0f) > 0.f) ? 1.f : 0.f;
            float2 o2; o2.x = s0; o2.y = s1;
            *(float2*)&out[ob + (size_t)u * (BBs * CCh * NP)] = o2;
            if (s0 != 0.f) mem0 = 0.f;
            if (s1 != 0.f) mem1 = 0.f;
        }
    }
}

// ---------------- TIM conv2 (grouped) + BN + fused LIF2 ----------------
// Block per (c, z=br*4+b), loops t with membrane in registers; writes spikes directly.
__global__ void tim_conv2_kernel(const float* __restrict__ sp, const float* __restrict__ wdn,
                                 const float* __restrict__ sc, const float* __restrict__ sh,
                                 float* __restrict__ out)
{
    __shared__ float sW[1080];
    __shared__ float sIn[12][18 * 19];
    int c  = blockIdx.x;
    int z  = blockIdx.y;
    int b  = z & 3;
    int br = z >> 2;
    int tid = threadIdx.x;

    for (int i = tid; i < 1080; i += 256) sW[i] = wdn[i];

    int h = tid >> 4, w = tid & 15;
    float mem = 0.f;

#pragma unroll 1
    for (int t = 0; t < 10; t++) {
        __syncthreads();
        for (int i = tid; i < 12 * 324; i += 256) {
            int pl = i / 324, rem = i % 324;
            int hh = rem / 18, ww = rem % 18;
            int r = pl / 3, dc = pl % 3;
            int u = t * 4 + r;
            int ci = c + dc - 1;
            int hy = hh - 1, wx = ww - 1;
            float v = 0.f;
            if (ci >= 0 && ci < CCh && hy >= 0 && hy < 16 && wx >= 0 && wx < 16)
                v = sp[(((size_t)(br * 40 + u) * BBs + b) * CCh + ci) * NP + hy * 16 + wx];
            sIn[pl][hh * 19 + ww] = v;
        }
        __syncthreads();

        float acc = 0.f;
#pragma unroll
        for (int r = 0; r < 4; r++) {
#pragma unroll
            for (int dc = 0; dc < 3; dc++) {
                const float* wr = &sW[(4 * t + r) * 27 + dc * 9];
                const float* pv = &sIn[r * 3 + dc][0];
#pragma unroll
                for (int dh = 0; dh < 3; dh++) {
                    const float* rp = &pv[(h + dh) * 19 + w];
                    acc += rp[0] * wr[dh * 3 + 0];
                    acc += rp[1] * wr[dh * 3 + 1];
                    acc += rp[2] * wr[dh * 3 + 2];
                }
            }
        }
        float yv = acc * sc[t] + sh[t];
        mem = mem + (yv - mem) * 0.5f;
        float spk = ((mem - 1.0f) > 0.f) ? 1.f : 0.f;
        out[(size_t)br * S_TBCN + (((size_t)t * BBs + b) * CCh + c) * NP + tid] = spk;
        if (spk != 0.f) mem = 0.f;
    }
}

// ---------------- LIF variants ----------------
__global__ void lif_kernel(const float* __restrict__ in, float* __restrict__ out,
                           int nChains, int stride, float vth)
{
    int i = blockIdx.x * blockDim.x + threadIdx.x;
    if (i >= nChains) return;
    float mem = 0.f;
    int p = i;
#pragma unroll
    for (int s = 0; s < 10; s++, p += stride) {
        float x = in[p];
        mem = mem + (x - mem) * 0.5f;
        float spk = ((mem - vth) > 0.f) ? 1.f : 0.f;
        out[p] = spk;
        if (spk != 0.f) mem = 0.f;
    }
}

__global__ void lif_resid_kernel(const float* __restrict__ in, const float* __restrict__ res,
                                 float* __restrict__ out, int nChains, int stride, float vth)
{
    int i = blockIdx.x * blockDim.x + threadIdx.x;
    if (i >= nChains) return;
    float mem = 0.f;
    int p = i;
#pragma unroll
    for (int s = 0; s < 10; s++, p += stride) {
        float x = in[p];
        mem = mem + (x - mem) * 0.5f;
        float spk = ((mem - vth) > 0.f) ? 1.f : 0.f;
        out[p] = res[p] + spk;
        if (spk != 0.f) mem = 0.f;
    }
}

// ---------------- KtV: per (t,b,head): 16x16 Gram over N ----------------
__global__ void ktv_kernel(const float* __restrict__ ks, const float* __restrict__ vs,
                           float* __restrict__ ktv)
{
    __shared__ float kT[16 * 257];
    __shared__ float vT[16 * 257];
    int tbh = blockIdx.x;
    int hh = tbh & 15;
    int tb = tbh >> 4;
    size_t base = ((size_t)tb * CCh + hh * 16) * NP;
    int tid = threadIdx.x;
    for (int i = tid; i < 16 * 256; i += 256) {
        int r = i >> 8, n = i & 255;
        kT[r * 257 + n] = ks[base + (size_t)r * NP + n];
        vT[r * 257 + n] = vs[base + (size_t)r * NP + n];
    }
    __syncthreads();
    int dd = tid >> 4, de = tid & 15;
    const float* kr = &kT[dd * 257];
    const float* vr = &vT[de * 257];
    float acc = 0.f;
#pragma unroll 8
    for (int n = 0; n < 256; n++) acc += kr[n] * vr[n];
    ktv[(size_t)tbh * 256 + dd * 16 + de] = acc;
}

// ---------------- attn out: o = 0.25 * Q (KtV) ----------------
__global__ void attn_o_kernel(const float* __restrict__ qs, const float* __restrict__ ktv,
                              float* __restrict__ o)
{
    __shared__ float sK[256];
    int tbh = blockIdx.x;
    int hh = tbh & 15;
    int tb = tbh >> 4;
    int tid = threadIdx.x;
    sK[tid] = ktv[(size_t)tbh * 256 + tid];
    __syncthreads();
    size_t base = ((size_t)tb * CCh + hh * 16) * NP + tid;
    float q[16];
#pragma unroll
    for (int d = 0; d < 16; d++) q[d] = qs[base + (size_t)d * NP];
#pragma unroll
    for (int dp = 0; dp < 16; dp++) {
        float acc = 0.f;
#pragma unroll
        for (int d = 0; d < 16; d++) acc += q[d] * sK[d * 16 + dp];
        o[base + (size_t)dp * NP] = acc * 0.25f;
    }
}

// ---------------- orchestration ----------------
extern "C" void kernel_launch(void* const* d_in, const int* in_sizes, int n_in,
                              void* d_out, int out_size)
{
    (void)in_sizes; (void)n_in; (void)out_size;
    const float* x        = (const float*)d_in[0];
    const float* q_w      = (const float*)d_in[1];
    const float* q_bn     = (const float*)d_in[2];
    const float* k_w      = (const float*)d_in[3];
    const float* k_bn     = (const float*)d_in[4];
    const float* v_w      = (const float*)d_in[5];
    const float* v_bn     = (const float*)d_in[6];
    const float* proj_w   = (const float*)d_in[7];
    const float* proj_bn  = (const float*)d_in[8];
    const float* tim_up_w = (const float*)d_in[9];
    const float* tim_bn1  = (const float*)d_in[10];
    const float* tim_dn_w = (const float*)d_in[11];
    const float* tim_bn2  = (const float*)d_in[12];
    const float* fc1_w    = (const float*)d_in[13];
    const float* fc1_b    = (const float*)d_in[14];
    const float* fc1_bn   = (const float*)d_in[15];
    const float* fc2_w    = (const float*)d_in[16];
    const float* fc2_b    = (const float*)d_in[17];
    const float* fc2_bn   = (const float*)d_in[18];
    float* outp = (float*)d_out;

    float *bufA, *bufB, *spk1, *spk2, *ybuf, *obuf, *hbuf, *ktvb, *wqkv;
    float *scal, *shif, *t1s, *t1h, *t2s, *t2h;
    cudaGetSymbolAddress((void**)&bufA, g_bufA);
    cudaGetSymbolAddress((void**)&bufB, g_bufB);
    cudaGetSymbolAddress((void**)&spk1, g_spk1);
    cudaGetSymbolAddress((void**)&spk2, g_spk2);
    cudaGetSymbolAddress((void**)&ybuf, g_y);
    cudaGetSymbolAddress((void**)&obuf, g_o);
    cudaGetSymbolAddress((void**)&hbuf, g_h);
    cudaGetSymbolAddress((void**)&ktvb, g_ktv);
    cudaGetSymbolAddress((void**)&wqkv, g_wqkv);
    cudaGetSymbolAddress((void**)&scal, g_scale);
    cudaGetSymbolAddress((void**)&shif, g_shift);
    cudaGetSymbolAddress((void**)&t1s,  g_t1s);
    cudaGetSymbolAddress((void**)&t1h,  g_t1h);
    cudaGetSymbolAddress((void**)&t2s,  g_t2s);
    cudaGetSymbolAddress((void**)&t2h,  g_t2h);

    // all setup in one launch: wqkv concat + every BN fold
    prep_all_kernel<<<779, 256>>>(q_w, k_w, v_w, wqkv,
                                  q_bn, k_bn, v_bn, proj_bn,
                                  fc1_bn, fc1_b, fc2_bn, fc2_b,
                                  tim_bn1, tim_bn2,
                                  scal, shif, t1s, t1h, t2s, t2h);

    // merged q/k/v GEMM: Out (tb, 768, n)
    gemm_bn_kernel<<<dim3(6, 2, TT*BBs), 256>>>(x, wqkv, bufA, 768, CCh,
                                                scal + SC_QKV, shif + SC_QKV);

    // TIM: conv1+BN+LIF1 (all branches), conv2+BN+LIF2 fused
    tim_conv1_kernel<<<dim3(CCh, BBs, 3), 256>>>(bufA, tim_up_w, t1s, t1h, spk1);
    tim_conv2_kernel<<<dim3(CCh, 12), 256>>>(spk1, tim_dn_w, t2s, t2h, spk2);

    // attention (linear, binary, exact): q=br0, k=br1, v=br2
    ktv_kernel<<<TT*BBs*16, 256>>>(spk2 + S_TBCN, spk2 + 2*S_TBCN, ktvb);
    attn_o_kernel<<<TT*BBs*16, 256>>>(spk2, ktvb, obuf);
    lif_kernel<<<(BCN + 255)/256, 256>>>(obuf, obuf, BCN, BCN, 0.5f);

    // projection + BN + lif; residual h = x + spikes
    gemm_bn_kernel<<<dim3(2, 2, TT*BBs), 256>>>(obuf, proj_w, ybuf, CCh, CCh,
                                                scal + SC_PROJ, shif + SC_PROJ);
    lif_resid_kernel<<<(BCN + 255)/256, 256>>>(ybuf, x, hbuf, BCN, BCN, 1.0f);

    // MLP
    gemm_bn_kernel<<<dim3(8, 2, TT*BBs), 256>>>(hbuf, fc1_w, bufA, HIDD, CCh,
                                                scal + SC_FC1, shif + SC_FC1);
    lif_kernel<<<(BHN + 255)/256, 256>>>(bufA, bufB, BHN, BHN, 1.0f);

    gemm_bn_kernel<<<dim3(2, 2, TT*BBs), 256>>>(bufB, fc2_w, ybuf, CCh, HIDD,
                                                scal + SC_FC2, shif + SC_FC2);
    lif_resid_kernel<<<(BCN + 255)/256, 256>>>(ybuf, hbuf, outp, BCN, BCN, 1.0f);
}

// round 14
// speedup vs baseline: 1.8193x; 1.0692x over previous
#include <cuda_runtime.h>
#include <math.h>

// ---------------- problem dims ----------------
#define TT    10
#define BBs   4
#define CCh   256
#define NP    256          // H*W = 16*16
#define TRR   40           // STEP*RATIO
#define HIDD  1024
#define EPSL  1e-5f

#define BCN   (BBs*CCh*NP)     // 262144 = 2^18
#define BHN   (BBs*HIDD*NP)    // 1048576
#define S_TBCN  (TT*BCN)       // 2,621,440
#define S_TRBCN (TRR*BBs*CCh*NP) // 10,485,760

// ---------------- scratch ----------------
__device__ float g_bufA[S_TRBCN];      // qkv gemm out / fc1 out
__device__ float g_bufB[S_TRBCN];      // fc1 spikes
__device__ float g_spk1[3*S_TRBCN];    // conv1 spikes, [br][u][b][c][n]
__device__ float g_spk2[3*S_TBCN];     // branch spikes, [br][t][b][c][n]
__device__ float g_y[S_TBCN];
__device__ float g_o[S_TBCN];
__device__ float g_h[S_TBCN];
__device__ float g_ktv[TT*BBs*16*256];
__device__ float g_wqkv[3*CCh*CCh];
__device__ float g_scale[2560];
__device__ float g_shift[2560];
__device__ float g_t1s[TRR], g_t1h[TRR];
__device__ float g_t2s[TT],  g_t2h[TT];

// scale/shift slice offsets
#define SC_QKV  0
#define SC_PROJ 768
#define SC_FC1  1024
#define SC_FC2  2048

// ---------------- merged prep: wqkv concat + ALL BN folds in one launch ----------------
__device__ __forceinline__ void fold_one(const float* __restrict__ bnp, const float* __restrict__ bias,
                                         int cnum, int i, float* __restrict__ s_, float* __restrict__ h_)
{
    if (i >= cnum) return;
    float g  = bnp[i];
    float be = bnp[cnum + i];
    float m  = bnp[2*cnum + i];
    float v  = bnp[3*cnum + i];
    float s  = g / sqrtf(v + EPSL);
    float sh = be - m * s;
    if (bias) sh += bias[i] * s;
    s_[i] = s;
    h_[i] = sh;
}

__global__ void prep_all_kernel(
    const float* __restrict__ qw, const float* __restrict__ kw, const float* __restrict__ vw,
    float* __restrict__ wqkv,
    const float* __restrict__ qbn, const float* __restrict__ kbn, const float* __restrict__ vbn,
    const float* __restrict__ projbn,
    const float* __restrict__ fc1bn, const float* __restrict__ fc1b,
    const float* __restrict__ fc2bn, const float* __restrict__ fc2b,
    const float* __restrict__ t1bn, const float* __restrict__ t2bn,
    float* __restrict__ scal, float* __restrict__ shif,
    float* __restrict__ t1s, float* __restrict__ t1h,
    float* __restrict__ t2s, float* __restrict__ t2h)
{
    int bx = blockIdx.x, tid = threadIdx.x;
    if (bx < 768) {
        int i = bx * 256 + tid;
        const int n = CCh * CCh;
        float v = (i < n) ? qw[i] : (i < 2*n) ? kw[i - n] : vw[i - 2*n];
        wqkv[i] = v;
        return;
    }
    int job = bx - 768;
    switch (job) {
        case 0:  fold_one(qbn,    nullptr, 256,  tid, scal + SC_QKV,       shif + SC_QKV);       break;
        case 1:  fold_one(kbn,    nullptr, 256,  tid, scal + SC_QKV + 256, shif + SC_QKV + 256); break;
        case 2:  fold_one(vbn,    nullptr, 256,  tid, scal + SC_QKV + 512, shif + SC_QKV + 512); break;
        case 3:  fold_one(projbn, nullptr, 256,  tid, scal + SC_PROJ,      shif + SC_PROJ);      break;
        case 4: case 5: case 6: case 7:
                 fold_one(fc1bn,  fc1b,    1024, (job - 4) * 256 + tid, scal + SC_FC1, shif + SC_FC1); break;
        case 8:  fold_one(fc2bn,  fc2b,    256,  tid, scal + SC_FC2,       shif + SC_FC2);       break;
        case 9:  fold_one(t1bn,   nullptr, TRR,  tid, t1s, t1h); break;
        case 10: fold_one(t2bn,   nullptr, TT,   tid, t2s, t2h); break;
    }
}

// ---------------- batched GEMM + BN epilogue ----------------
// CTA tile 128(o) x 128(n), BK=8, 256 threads, microtile 16x4.
#define APITCH 132
__global__ __launch_bounds__(256, 2)
void gemm_bn_kernel(const float* __restrict__ In, const float* __restrict__ Wm,
                    float* __restrict__ Out, int O, int K,
                    const float* __restrict__ scale, const float* __restrict__ shift)
{
    __shared__ __align__(16) float sA[2][8][APITCH];   // [buf][k][o] padded
    __shared__ __align__(16) float sB[2][8][128];      // [buf][k][n]
    int tb = blockIdx.z;
    int oBase = blockIdx.x * 128;
    int nBase = blockIdx.y * 128;
    const float* Bp = In + (size_t)tb * K * NP + nBase;
    float* Cp = Out + (size_t)tb * O * NP + nBase;
    int tid = threadIdx.x;
    int lane = tid & 31, warp = tid >> 5;

    int aro = tid >> 1, akq = (tid & 1) * 4;
    int bk  = tid >> 5, bn  = (tid & 31) * 4;

    const float* wp = &Wm[(size_t)(oBase + aro) * K + akq];
    const float* bp = &Bp[(size_t)bk * NP + bn];

    float4 av = *(const float4*)wp;
    float4 bv = *(const float4*)bp;
    sA[0][akq + 0][aro] = av.x; sA[0][akq + 1][aro] = av.y;
    sA[0][akq + 2][aro] = av.z; sA[0][akq + 3][aro] = av.w;
    *(float4*)&sB[0][bk][bn] = bv;
    __syncthreads();

    float acc[16][4];
#pragma unroll
    for (int i = 0; i < 16; i++)
#pragma unroll
        for (int j = 0; j < 4; j++) acc[i][j] = 0.f;

    int nk = K >> 3;
    for (int kt = 0; kt < nk; kt++) {
        int cur = kt & 1;
        if (kt + 1 < nk) {
            av = *(const float4*)(wp + (kt + 1) * 8);
            bv = *(const float4*)(bp + (size_t)(kt + 1) * 8 * NP);
        }
#pragma unroll
        for (int kk = 0; kk < 8; kk++) {
            float4 b  = *(const float4*)&sB[cur][kk][bn];
            float4 a0 = *(const float4*)&sA[cur][kk][warp * 16 + 0];
            float4 a1 = *(const float4*)&sA[cur][kk][warp * 16 + 4];
            float4 a2 = *(const float4*)&sA[cur][kk][warp * 16 + 8];
            float4 a3 = *(const float4*)&sA[cur][kk][warp * 16 + 12];
#define ROW(i, s) \
            acc[i][0] += (s) * b.x; acc[i][1] += (s) * b.y; \
            acc[i][2] += (s) * b.z; acc[i][3] += (s) * b.w;
            ROW(0, a0.x)  ROW(1, a0.y)  ROW(2, a0.z)  ROW(3, a0.w)
            ROW(4, a1.x)  ROW(5, a1.y)  ROW(6, a1.z)  ROW(7, a1.w)
            ROW(8, a2.x)  ROW(9, a2.y)  ROW(10, a2.z) ROW(11, a2.w)
            ROW(12, a3.x) ROW(13, a3.y) ROW(14, a3.z) ROW(15, a3.w)
#undef ROW
        }
        if (kt + 1 < nk) {
            int nxt = cur ^ 1;
            sA[nxt][akq + 0][aro] = av.x; sA[nxt][akq + 1][aro] = av.y;
            sA[nxt][akq + 2][aro] = av.z; sA[nxt][akq + 3][aro] = av.w;
            *(float4*)&sB[nxt][bk][bn] = bv;
        }
        __syncthreads();
    }

#pragma unroll
    for (int i = 0; i < 16; i++) {
        int o = oBase + warp * 16 + i;
        float sc = scale[o], sh = shift[o];
        float4 r;
        r.x = acc[i][0] * sc + sh; r.y = acc[i][1] * sc + sh;
        r.z = acc[i][2] * sc + sh; r.w = acc[i][3] * sc + sh;
        *(float4*)&Cp[(size_t)o * NP + lane * 4] = r;
    }
}

// ---------------- TIM conv1 + BN + fused LIF1, pixel-pair microtile, hoisted indexing ----
// Thread: uh = tid>>7 selects 20 u's = chains r in {2uh, 2uh+1}; pp = tid&127 selects pixel pair.
// Weight smem permuted: sW[tap*40 + pos(u)], pos(u) = (r>>1)*20 + s*2 + (r&1), u = 4s+r.
__global__ __launch_bounds__(256)
void tim_conv1_kernel(const float* __restrict__ in, const float* __restrict__ wup,
                      const float* __restrict__ sc, const float* __restrict__ sh,
                      float* __restrict__ out)
{
    __shared__ __align__(16) float sW[2][1080];
    __shared__ float sIn[2][3 * 342];     // [dc][18 rows x pitch 19]
    __shared__ float sSc[40], sSh[40];
    int c  = blockIdx.x;
    int b  = blockIdx.y;
    int br = blockIdx.z;
    int tid = threadIdx.x;
    const float* inb = in + ((size_t)b * 768 + br * 256) * NP;

    if (tid < 40) { sSc[tid] = sc[tid]; sSh[tid] = sh[tid]; }

    // ---- hoisted staging descriptors (t-invariant) ----
    int giOff[4], siOff[4];
#pragma unroll
    for (int j = 0; j < 4; j++) {
        int i = tid + j * 256;
        siOff[j] = -1; giOff[j] = -1;
        if (i < 972) {
            int dc = i / 324, rem = i % 324;
            int hh = rem / 18, ww = rem % 18;
            int ci = c + dc - 1;
            int hy = hh - 1, wx = ww - 1;
            siOff[j] = dc * 342 + hh * 19 + ww;
            if (ci >= 0 && ci < CCh && hy >= 0 && hy < 16 && wx >= 0 && wx < 16)
                giOff[j] = ci * NP + hy * 16 + wx;
        }
    }
    int gwOff[5], swOff[5];
#pragma unroll
    for (int j = 0; j < 5; j++) {
        int i = tid + j * 256;
        swOff[j] = -1; gwOff[j] = 0;
        if (i < 1080) {
            int u = i % 40, tap = i / 40;
            int pos = ((u & 3) >> 1) * 20 + (u >> 2) * 2 + (u & 1);
            swOff[j] = tap * 40 + pos;
            gwOff[j] = u * 270 + tap;
        }
    }

    // ---- prologue: stage t=0 ----
    {
        float ip[4], wpre[5];
#pragma unroll
        for (int j = 0; j < 4; j++) ip[j] = (giOff[j] >= 0) ? inb[giOff[j]] : 0.f;
#pragma unroll
        for (int j = 0; j < 5; j++) wpre[j] = (swOff[j] >= 0) ? wup[gwOff[j]] : 0.f;
#pragma unroll
        for (int j = 0; j < 4; j++) if (siOff[j] >= 0) sIn[0][siOff[j]] = ip[j];
#pragma unroll
        for (int j = 0; j < 5; j++) if (swOff[j] >= 0) sW[0][swOff[j]] = wpre[j];
    }
    __syncthreads();

    int uh = tid >> 7;            // 0/1: which 20-u half
    int pp = tid & 127;           // pixel pair index
    int h = pp >> 3, w0 = (pp & 7) * 2;

    float acc[2][20];
#pragma unroll
    for (int px = 0; px < 2; px++)
#pragma unroll
        for (int j = 0; j < 20; j++) acc[px][j] = 0.f;

#pragma unroll 1
    for (int t = 0; t < 10; t++) {
        int cur = t & 1;
        float ip[4], wpre[5];
        if (t < 9) {
            const float* inb2 = inb + (size_t)(t + 1) * (BBs * 768 * NP);
            int wofs = (t + 1) * 27;
#pragma unroll
            for (int j = 0; j < 4; j++) ip[j] = (giOff[j] >= 0) ? inb2[giOff[j]] : 0.f;
#pragma unroll
            for (int j = 0; j < 5; j++) wpre[j] = (swOff[j] >= 0) ? wup[gwOff[j] + wofs] : 0.f;
        }

        // ---- compute t ----
#pragma unroll
        for (int dc = 0; dc < 3; dc++) {
#pragma unroll
            for (int dh = 0; dh < 3; dh++) {
                const float* rowp = &sIn[cur][dc * 342 + (h + dh) * 19 + w0];
                float iv[4] = {rowp[0], rowp[1], rowp[2], rowp[3]};
#pragma unroll
                for (int dw = 0; dw < 3; dw++) {
                    float v0 = iv[dw], v1 = iv[dw + 1];
                    const float4* wq = (const float4*)&sW[cur][((dc * 3 + dh) * 3 + dw) * 40 + uh * 20];
#pragma unroll
                    for (int j = 0; j < 5; j++) {
                        float4 w4 = wq[j];
                        acc[0][4*j + 0] += v0 * w4.x; acc[1][4*j + 0] += v1 * w4.x;
                        acc[0][4*j + 1] += v0 * w4.y; acc[1][4*j + 1] += v1 * w4.y;
                        acc[0][4*j + 2] += v0 * w4.z; acc[1][4*j + 2] += v1 * w4.z;
                        acc[0][4*j + 3] += v0 * w4.w; acc[1][4*j + 3] += v1 * w4.w;
                    }
                }
            }
        }

        if (t < 9) {
            int nxt = cur ^ 1;
            __syncthreads();
#pragma unroll
            for (int j = 0; j < 4; j++) if (siOff[j] >= 0) sIn[nxt][siOff[j]] = ip[j];
#pragma unroll
            for (int j = 0; j < 5; j++) if (swOff[j] >= 0) sW[nxt][swOff[j]] = wpre[j];
        }
        __syncthreads();
    }

    // ---- BN + fused LIF1 epilogue (chains r = 2uh + r01) ----
    size_t ob = ((size_t)(br * 40) * BBs + b) * CCh * NP + (size_t)c * NP + 2 * pp;
#pragma unroll
    for (int r01 = 0; r01 < 2; r01++) {
        int r = 2 * uh + r01;
        float mem0 = 0.f, mem1 = 0.f;
#pragma unroll
        for (int s = 0; s < 10; s++) {
            int u = 4 * s + r;
            int j = 2 * s + r01;
            float y0 = acc[0][j] * sSc[u] + sSh[u];
            float y1 = acc[1][j] * sSc[u] + sSh[u];
            mem0 = mem0 + (y0 - mem0) * 0.5f;
            mem1 = mem1 + (y1 - mem1) * 0.5f;
            float s0 = ((mem0 - 1.0f) > 0.f) ? 1.f : 0.f;
            float s1 = ((mem1 - 1.0f) > 0.f) ? 1.f : 0.f;
            float2 o2; o2.x = s0; o2.y = s1;
            *(float2*)&out[ob + (size_t)u * (BBs * CCh * NP)] = o2;
            if (s0 != 0.f) mem0 = 0.f;
            if (s1 != 0.f) mem1 = 0.f;
        }
    }
}

// ---------------- TIM conv2 (grouped) + BN + fused LIF2, hoisted indexing ----------------
// Block per (c, z=br*4+b), loops t with membrane in registers; writes spikes directly.
__global__ __launch_bounds__(256)
void tim_conv2_kernel(const float* __restrict__ sp, const float* __restrict__ wdn,
                      const float* __restrict__ sc, const float* __restrict__ sh,
                      float* __restrict__ out)
{
    __shared__ float sW[1080];
    __shared__ float sIn[12 * 342];
    int c  = blockIdx.x;
    int z  = blockIdx.y;
    int b  = z & 3;
    int br = z >> 2;
    int tid = threadIdx.x;

    for (int i = tid; i < 1080; i += 256) sW[i] = wdn[i];

    // ---- hoisted staging descriptors (t-invariant; gmem advances by t*stride) ----
    int sOff[16], gOff[16];
#pragma unroll
    for (int j = 0; j < 16; j++) {
        int i = tid + j * 256;
        sOff[j] = -1; gOff[j] = -1;
        if (i < 3888) {
            int pl = i / 324, rem = i % 324;
            int hh = rem / 18, ww = rem % 18;
            int r = pl / 3, dc = pl % 3;
            int ci = c + dc - 1;
            int hy = hh - 1, wx = ww - 1;
            sOff[j] = pl * 342 + hh * 19 + ww;
            if (ci >= 0 && ci < CCh && hy >= 0 && hy < 16 && wx >= 0 && wx < 16)
                gOff[j] = (((br * 40 + r) * BBs + b) * CCh + ci) * NP + hy * 16 + wx;
        }
    }

    int h = tid >> 4, w = tid & 15;
    float mem = 0.f;
    float pf[16];

    // stage t=0
#pragma unroll
    for (int j = 0; j < 16; j++) pf[j] = (gOff[j] >= 0) ? sp[gOff[j]] : 0.f;
#pragma unroll
    for (int j = 0; j < 16; j++) if (sOff[j] >= 0) sIn[sOff[j]] = pf[j];
    __syncthreads();

#pragma unroll 1
    for (int t = 0; t < 10; t++) {
        if (t < 9) {
            const float* spt = sp + (size_t)(t + 1) * (4 * BBs * CCh * NP);
#pragma unroll
            for (int j = 0; j < 16; j++) pf[j] = (gOff[j] >= 0) ? spt[gOff[j]] : 0.f;
        }

        float acc = 0.f;
#pragma unroll
        for (int r = 0; r < 4; r++) {
#pragma unroll
            for (int dc = 0; dc < 3; dc++) {
                const float* wr = &sW[(4 * t + r) * 27 + dc * 9];
                const float* pv = &sIn[(r * 3 + dc) * 342];
#pragma unroll
                for (int dh = 0; dh < 3; dh++) {
                    const float* rp = &pv[(h + dh) * 19 + w];
                    acc += rp[0] * wr[dh * 3 + 0];
                    acc += rp[1] * wr[dh * 3 + 1];
                    acc += rp[2] * wr[dh * 3 + 2];
                }
            }
        }
        float yv = acc * sc[t] + sh[t];
        mem = mem + (yv - mem) * 0.5f;
        float spk = ((mem - 1.0f) > 0.f) ? 1.f : 0.f;
        out[(size_t)br * S_TBCN + (((size_t)t * BBs + b) * CCh + c) * NP + tid] = spk;
        if (spk != 0.f) mem = 0.f;

        if (t < 9) {
            __syncthreads();
#pragma unroll
            for (int j = 0; j < 16; j++) if (sOff[j] >= 0) sIn[sOff[j]] = pf[j];
            __syncthreads();
        }
    }
}

// ---------------- LIF variants ----------------
__global__ void lif_kernel(const float* __restrict__ in, float* __restrict__ out,
                           int nChains, int stride, float vth)
{
    int i = blockIdx.x * blockDim.x + threadIdx.x;
    if (i >= nChains) return;
    float mem = 0.f;
    int p = i;
#pragma unroll
    for (int s = 0; s < 10; s++, p += stride) {
        float x = in[p];
        mem = mem + (x - mem) * 0.5f;
        float spk = ((mem - vth) > 0.f) ? 1.f : 0.f;
        out[p] = spk;
        if (spk != 0.f) mem = 0.f;
    }
}

__global__ void lif_resid_kernel(const float* __restrict__ in, const float* __restrict__ res,
                                 float* __restrict__ out, int nChains, int stride, float vth)
{
    int i = blockIdx.x * blockDim.x + threadIdx.x;
    if (i >= nChains) return;
    float mem = 0.f;
    int p = i;
#pragma unroll
    for (int s = 0; s < 10; s++, p += stride) {
        float x = in[p];
        mem = mem + (x - mem) * 0.5f;
        float spk = ((mem - vth) > 0.f) ? 1.f : 0.f;
        out[p] = res[p] + spk;
        if (spk != 0.f) mem = 0.f;
    }
}

// ---------------- KtV: per (t,b,head): 16x16 Gram over N ----------------
__global__ void ktv_kernel(const float* __restrict__ ks, const float* __restrict__ vs,
                           float* __restrict__ ktv)
{
    __shared__ float kT[16 * 257];
    __shared__ float vT[16 * 257];
    int tbh = blockIdx.x;
    int hh = tbh & 15;
    int tb = tbh >> 4;
    size_t base = ((size_t)tb * CCh + hh * 16) * NP;
    int tid = threadIdx.x;
    for (int i = tid; i < 16 * 256; i += 256) {
        int r = i >> 8, n = i & 255;
        kT[r * 257 + n] = ks[base + (size_t)r * NP + n];
        vT[r * 257 + n] = vs[base + (size_t)r * NP + n];
    }
    __syncthreads();
    int dd = tid >> 4, de = tid & 15;
    const float* kr = &kT[dd * 257];
    const float* vr = &vT[de * 257];
    float acc = 0.f;
#pragma unroll 8
    for (int n = 0; n < 256; n++) acc += kr[n] * vr[n];
    ktv[(size_t)tbh * 256 + dd * 16 + de] = acc;
}

// ---------------- attn out: o = 0.25 * Q (KtV) ----------------
__global__ void attn_o_kernel(const float* __restrict__ qs, const float* __restrict__ ktv,
                              float* __restrict__ o)
{
    __shared__ float sK[256];
    int tbh = blockIdx.x;
    int hh = tbh & 15;
    int tb = tbh >> 4;
    int tid = threadIdx.x;
    sK[tid] = ktv[(size_t)tbh * 256 + tid];
    __syncthreads();
    size_t base = ((size_t)tb * CCh + hh * 16) * NP + tid;
    float q[16];
#pragma unroll
    for (int d = 0; d < 16; d++) q[d] = qs[base + (size_t)d * NP];
#pragma unroll
    for (int dp = 0; dp < 16; dp++) {
        float acc = 0.f;
#pragma unroll
        for (int d = 0; d < 16; d++) acc += q[d] * sK[d * 16 + dp];
        o[base + (size_t)dp * NP] = acc * 0.25f;
    }
}

// ---------------- orchestration ----------------
extern "C" void kernel_launch(void* const* d_in, const int* in_sizes, int n_in,
                              void* d_out, int out_size)
{
    (void)in_sizes; (void)n_in; (void)out_size;
    const float* x        = (const float*)d_in[0];
    const float* q_w      = (const float*)d_in[1];
    const float* q_bn     = (const float*)d_in[2];
    const float* k_w      = (const float*)d_in[3];
    const float* k_bn     = (const float*)d_in[4];
    const float* v_w      = (const float*)d_in[5];
    const float* v_bn     = (const float*)d_in[6];
    const float* proj_w   = (const float*)d_in[7];
    const float* proj_bn  = (const float*)d_in[8];
    const float* tim_up_w = (const float*)d_in[9];
    const float* tim_bn1  = (const float*)d_in[10];
    const float* tim_dn_w = (const float*)d_in[11];
    const float* tim_bn2  = (const float*)d_in[12];
    const float* fc1_w    = (const float*)d_in[13];
    const float* fc1_b    = (const float*)d_in[14];
    const float* fc1_bn   = (const float*)d_in[15];
    const float* fc2_w    = (const float*)d_in[16];
    const float* fc2_b    = (const float*)d_in[17];
    const float* fc2_bn   = (const float*)d_in[18];
    float* outp = (float*)d_out;

    float *bufA, *bufB, *spk1, *spk2, *ybuf, *obuf, *hbuf, *ktvb, *wqkv;
    float *scal, *shif, *t1s, *t1h, *t2s, *t2h;
    cudaGetSymbolAddress((void**)&bufA, g_bufA);
    cudaGetSymbolAddress((void**)&bufB, g_bufB);
    cudaGetSymbolAddress((void**)&spk1, g_spk1);
    cudaGetSymbolAddress((void**)&spk2, g_spk2);
    cudaGetSymbolAddress((void**)&ybuf, g_y);
    cudaGetSymbolAddress((void**)&obuf, g_o);
    cudaGetSymbolAddress((void**)&hbuf, g_h);
    cudaGetSymbolAddress((void**)&ktvb, g_ktv);
    cudaGetSymbolAddress((void**)&wqkv, g_wqkv);
    cudaGetSymbolAddress((void**)&scal, g_scale);
    cudaGetSymbolAddress((void**)&shif, g_shift);
    cudaGetSymbolAddress((void**)&t1s,  g_t1s);
    cudaGetSymbolAddress((void**)&t1h,  g_t1h);
    cudaGetSymbolAddress((void**)&t2s,  g_t2s);
    cudaGetSymbolAddress((void**)&t2h,  g_t2h);

    // all setup in one launch: wqkv concat + every BN fold
    prep_all_kernel<<<779, 256>>>(q_w, k_w, v_w, wqkv,
                                  q_bn, k_bn, v_bn, proj_bn,
                                  fc1_bn, fc1_b, fc2_bn, fc2_b,
                                  tim_bn1, tim_bn2,
                                  scal, shif, t1s, t1h, t2s, t2h);

    // merged q/k/v GEMM: Out (tb, 768, n)
    gemm_bn_kernel<<<dim3(6, 2, TT*BBs), 256>>>(x, wqkv, bufA, 768, CCh,
                                                scal + SC_QKV, shif + SC_QKV);

    // TIM: conv1+BN+LIF1 (all branches), conv2+BN+LIF2 fused
    tim_conv1_kernel<<<dim3(CCh, BBs, 3), 256>>>(bufA, tim_up_w, t1s, t1h, spk1);
    tim_conv2_kernel<<<dim3(CCh, 12), 256>>>(spk1, tim_dn_w, t2s, t2h, spk2);

    // attention (linear, binary, exact): q=br0, k=br1, v=br2
    ktv_kernel<<<TT*BBs*16, 256>>>(spk2 + S_TBCN, spk2 + 2*S_TBCN, ktvb);
    attn_o_kernel<<<TT*BBs*16, 256>>>(spk2, ktvb, obuf);
    lif_kernel<<<(BCN + 255)/256, 256>>>(obuf, obuf, BCN, BCN, 0.5f);

    // projection + BN + lif; residual h = x + spikes
    gemm_bn_kernel<<<dim3(2, 2, TT*BBs), 256>>>(obuf, proj_w, ybuf, CCh, CCh,
                                                scal + SC_PROJ, shif + SC_PROJ);
    lif_resid_kernel<<<(BCN + 255)/256, 256>>>(ybuf, x, hbuf, BCN, BCN, 1.0f);

    // MLP
    gemm_bn_kernel<<<dim3(8, 2, TT*BBs), 256>>>(hbuf, fc1_w, bufA, HIDD, CCh,
                                                scal + SC_FC1, shif + SC_FC1);
    lif_kernel<<<(BHN + 255)/256, 256>>>(bufA, bufB, BHN, BHN, 1.0f);

    gemm_bn_kernel<<<dim3(2, 2, TT*BBs), 256>>>(bufB, fc2_w, ybuf, CCh, HIDD,
                                                scal + SC_FC2, shif + SC_FC2);
    lif_resid_kernel<<<(BCN + 255)/256, 256>>>(ybuf, hbuf, outp, BCN, BCN, 1.0f);
}